// round 12
// baseline (speedup 1.0000x reference)
#include <cuda_runtime.h>
#include <cuda_bf16.h>
#include <math.h>
#include <stdint.h>

#define Bc 8
#define Mc 8192
#define Sc 128
#define Dc 512
#define Qc 32
#define Hc 8
#define HDc 64
#define HQc 256

#define OFF_R 0
#define OFF_A (Bc*Qc*Dc)
#define OFF_G (OFF_A + Bc*Qc*Mc)
#define OFF_Q (OFF_G + Bc*Qc)

__device__ float g_pooled[Bc*Dc];
__device__ float g_cq[Bc*Dc];
__device__ float g_qs[Bc*Qc*Dc];
__device__ float g_qkb[Bc*HQc];
__device__ float g_attn[(size_t)Bc*HQc*Mc];          // compacted raw scores
__device__ float g_ctxp[8][(size_t)Bc*HQc*Dc];
__device__ int   g_midx[Bc][Mc];
__device__ int   g_cnt[Bc];
__device__ int   g_kpad[Bc];
__device__ __align__(16) __nv_bfloat16 g_A1h[(size_t)Bc*HQc*Dc];
__device__ __align__(16) __nv_bfloat16 g_A1l[(size_t)Bc*HQc*Dc];
__device__ __align__(16) __nv_bfloat16 g_B1h[(size_t)Bc*Mc*Dc];    // compacted memory rows
__device__ __align__(16) __nv_bfloat16 g_B1l[(size_t)Bc*Mc*Dc];
__device__ __align__(16) __nv_bfloat16 g_A2h[(size_t)Bc*HQc*Mc];   // compacted attn
__device__ __align__(16) __nv_bfloat16 g_A2l[(size_t)Bc*HQc*Mc];
__device__ __align__(16) __nv_bfloat16 g_B2h[(size_t)Bc*Dc*Mc];    // compacted memory^T
__device__ __align__(16) __nv_bfloat16 g_B2l[(size_t)Bc*Dc*Mc];

__device__ __forceinline__ void cvt8(const float* v, uint4* hi, uint4* lo){
    union { uint4 u; __nv_bfloat16 h[8]; } a, b;
    #pragma unroll
    for (int j=0;j<8;j++){
        float x = v[j];
        __nv_bfloat16 h = __float2bfloat16(x);
        a.h[j] = h;
        b.h[j] = __float2bfloat16(x - __bfloat162float(h));
    }
    *hi = a.u; *lo = b.u;
}
__device__ __forceinline__ uint32_t smem_u32(const void* p){
    uint32_t a;
    asm("{ .reg .u64 t; cvta.to.shared.u64 t, %1; cvt.u32.u64 %0, t; }" : "=r"(a) : "l"(p));
    return a;
}
__device__ __forceinline__ void cp16(uint32_t dst, const void* src){
    asm volatile("cp.async.cg.shared.global [%0], [%1], 16;" :: "r"(dst), "l"(src));
}
__device__ __forceinline__ void cp_commit(){ asm volatile("cp.async.commit_group;" ::: "memory"); }
__device__ __forceinline__ void cp_wait1(){ asm volatile("cp.async.wait_group 1;" ::: "memory"); }
__device__ __forceinline__ void ldm4(uint32_t* r, uint32_t a){
    asm volatile("ldmatrix.sync.aligned.m8n8.x4.shared.b16 {%0,%1,%2,%3}, [%4];"
      : "=r"(r[0]),"=r"(r[1]),"=r"(r[2]),"=r"(r[3]) : "r"(a));
}
__device__ __forceinline__ void mma16816(float* c, const uint32_t* a, const uint32_t* b){
    asm volatile("mma.sync.aligned.m16n8k16.row.col.f32.bf16.bf16.f32 "
      "{%0,%1,%2,%3}, {%4,%5,%6,%7}, {%8,%9}, {%0,%1,%2,%3};"
      : "+f"(c[0]),"+f"(c[1]),"+f"(c[2]),"+f"(c[3])
      : "r"(a[0]),"r"(a[1]),"r"(a[2]),"r"(a[3]), "r"(b[0]),"r"(b[1]));
}

// ---------- mask prefix-scan ----------
__global__ __launch_bounds__(1024) void k_mask_scan(const int* __restrict__ mask){
    int b = blockIdx.x, t = threadIdx.x;
    __shared__ int wsum[32];
    for (int j = t; j < Mc; j += 1024) g_midx[b][j] = 0;
    __syncthreads();
    int bits[8]; int loc = 0;
    #pragma unroll
    for (int i = 0; i < 8; i++) { bits[i] = (mask[(size_t)b*Mc + t*8 + i] != 0); loc += bits[i]; }
    int lane = t & 31, w = t >> 5;
    int x = loc;
    #pragma unroll
    for (int o = 1; o < 32; o <<= 1) { int y = __shfl_up_sync(0xffffffffu, x, o); if (lane >= o) x += y; }
    if (lane == 31) wsum[w] = x;
    __syncthreads();
    if (t < 32) {
        int y = wsum[t];
        #pragma unroll
        for (int o = 1; o < 32; o <<= 1) { int z = __shfl_up_sync(0xffffffffu, y, o); if (t >= o) y += z; }
        wsum[t] = y;
    }
    __syncthreads();
    int base = x - loc + (w ? wsum[w-1] : 0);
    #pragma unroll
    for (int i = 0; i < 8; i++) if (bits[i]) g_midx[b][base++] = t*8 + i;
    if (t == 0) { int cnt = wsum[31]; g_cnt[b] = cnt; g_kpad[b] = ((cnt + 127) >> 7) << 7; }
}

// ---------- small kernels ----------
__global__ void k_pooled(const float* __restrict__ ctx) {
    int b = blockIdx.x, d = threadIdx.x;
    const float* p = ctx + (size_t)b*Sc*Dc + d;
    float s = 0.f;
    #pragma unroll 8
    for (int i = 0; i < Sc; i++) s += p[(size_t)i*Dc];
    g_pooled[b*Dc + d] = s * (1.0f/Sc);
}
__global__ void k_cq_gates(const float* __restrict__ ctx_w, const float* __restrict__ ctx_b,
                           const float* __restrict__ gate_w, const float* __restrict__ gate_b,
                           float* __restrict__ out) {
    int b = blockIdx.x, t = threadIdx.x;
    __shared__ __align__(16) float pool[Dc];
    pool[t] = g_pooled[b*Dc + t];
    __syncthreads();
    const float4* p4 = (const float4*)pool;
    const float4* w = (const float4*)(ctx_w + (size_t)t*Dc);
    float acc = ctx_b[t];
    #pragma unroll 8
    for (int e = 0; e < Dc/4; e++) {
        float4 wv = w[e], pv = p4[e];
        acc += wv.x*pv.x + wv.y*pv.y + wv.z*pv.z + wv.w*pv.w;
    }
    g_cq[b*Dc + t] = acc;
    if (t < Qc) {
        const float4* gw = (const float4*)(gate_w + (size_t)t*Dc);
        float a2 = gate_b[t];
        #pragma unroll 8
        for (int e = 0; e < Dc/4; e++) {
            float4 wv = gw[e], pv = p4[e];
            a2 += wv.x*pv.x + wv.y*pv.y + wv.z*pv.z + wv.w*pv.w;
        }
        out[OFF_G + b*Qc + t] = 1.0f/(1.0f + expf(-a2));
    }
}
__global__ void k_queries_qs(const float* __restrict__ qp, const float* __restrict__ in_w,
                             const float* __restrict__ in_b, float* __restrict__ out) {
    int bid = blockIdx.x; int b = bid >> 5, q = bid & 31; int t = threadIdx.x;
    __shared__ __align__(16) float qrow[Dc];
    __shared__ __align__(16) float qs_s[Dc];
    for (int i = t; i < Dc; i += 256) {
        float v = qp[q*Dc + i] + g_cq[b*Dc + i];
        qrow[i] = v;
        out[OFF_Q + (size_t)bid*Dc + i] = v;
    }
    __syncthreads();
    const float4* q4 = (const float4*)qrow;
    for (int f = t; f < Dc; f += 256) {
        const float4* w = (const float4*)(in_w + (size_t)f*Dc);
        float acc = in_b[f];
        #pragma unroll 8
        for (int e = 0; e < Dc/4; e++) {
            float4 wv = w[e], pv = q4[e];
            acc += wv.x*pv.x + wv.y*pv.y + wv.z*pv.z + wv.w*pv.w;
        }
        float v = acc * 0.125f;
        qs_s[f] = v;
        g_qs[(size_t)bid*Dc + f] = v;
    }
    __syncthreads();
    if (t < Hc) {
        float s = 0.f;
        #pragma unroll
        for (int hd = 0; hd < HDc; hd++) s += qs_s[t*HDc + hd] * in_b[Dc + t*HDc + hd];
        g_qkb[b*HQc + t*Qc + q] = s;
    }
}
__global__ __launch_bounds__(128) void k_qk(const float* __restrict__ in_w) {
    int h = blockIdx.x, r0 = blockIdx.y*16, t = threadIdx.x;
    int c = blockIdx.z*128 + t;
    __shared__ float A[16][65];
    for (int j = t; j < 16*64; j += 128) A[j>>6][j&63] = g_qs[(size_t)(r0 + (j>>6))*Dc + h*HDc + (j&63)];
    __syncthreads();
    float acc[16];
    #pragma unroll
    for (int r = 0; r < 16; r++) acc[r] = 0.f;
    const float* wk = in_w + (size_t)(Dc + h*HDc)*Dc;
    #pragma unroll 8
    for (int hd = 0; hd < HDc; hd++) {
        float w = wk[(size_t)hd*Dc + c];
        #pragma unroll
        for (int r = 0; r < 16; r++) acc[r] += A[r][hd]*w;
    }
    #pragma unroll
    for (int r = 0; r < 16; r++) {
        int bq = r0 + r; int b = bq >> 5, q = bq & 31;
        size_t idx = ((size_t)b*HQc + h*Qc + q)*Dc + c;
        float x = acc[r];
        __nv_bfloat16 hi = __float2bfloat16(x);
        g_A1h[idx] = hi;
        g_A1l[idx] = __float2bfloat16(x - __bfloat162float(hi));
    }
}

// ---------- gathered conversion: compacted B1 + B2, per half-batch ----------
__global__ __launch_bounds__(256) void k_convT(const float* __restrict__ mem, int bOff) {
    int mb = blockIdx.x, db = blockIdx.y, b = blockIdx.z + bOff, t = threadIdx.x;
    int m0 = mb*64;
    if (m0 >= g_kpad[b]) return;
    int cnt = g_cnt[b];
    __shared__ int sidx[64];
    __shared__ float s[64][129];
    if (t < 64) { int j = m0 + t; sidx[t] = (j < cnt) ? g_midx[b][j] : 0; }
    __syncthreads();
    int d0 = db*128;
    for (int it = 0; it < 8; it++) {
        int idx = t + it*256; int r = idx >> 5, c4 = idx & 31;
        float4 v = *(const float4*)(mem + ((size_t)b*Mc + sidx[r])*Dc + d0 + c4*4);
        s[r][c4*4+0] = v.x; s[r][c4*4+1] = v.y; s[r][c4*4+2] = v.z; s[r][c4*4+3] = v.w;
    }
    __syncthreads();
    {
        int r = t >> 2, ds = (t & 3)*32;
        size_t base = ((size_t)b*Mc + m0 + r)*Dc + d0 + ds;
        #pragma unroll
        for (int g = 0; g < 4; g++) {
            float v[8];
            #pragma unroll
            for (int j = 0; j < 8; j++) v[j] = s[r][ds + g*8 + j];
            uint4 hi, lo; cvt8(v, &hi, &lo);
            *(uint4*)(g_B1h + base + g*8) = hi;
            *(uint4*)(g_B1l + base + g*8) = lo;
        }
    }
    for (int it = 0; it < 2; it++) {
        int u = t + it*256; int dl = u >> 2, g = u & 3;
        float v[16];
        #pragma unroll
        for (int j = 0; j < 16; j++) v[j] = s[g*16 + j][dl];
        uint4 h0, l0, h1, l1;
        cvt8(v, &h0, &l0); cvt8(v + 8, &h1, &l1);
        size_t base = ((size_t)b*Dc + d0 + dl)*Mc + m0 + g*16;
        *(uint4*)(g_B2h + base)     = h0;
        *(uint4*)(g_B2h + base + 8) = h1;
        *(uint4*)(g_B2l + base)     = l0;
        *(uint4*)(g_B2l + base + 8) = l1;
    }
}

// ---------- HMMA GEMM (NT), 128x128 tile, BK=32, bf16 split-3, half-batch ----------
#define TPAD 80
#define TILE_B 10240
#define STG   40960
#define GSMEM (2*STG)
template<int MODE>
__global__ __launch_bounds__(256, 1) void k_gemm(int bOff) {
    extern __shared__ __align__(128) unsigned char smraw[];
    uint32_t sb = smem_u32(smraw);
    int tid = threadIdx.x, lane = tid & 31, wid = tid >> 5;
    int wm0 = (wid & 1)*64, wn0 = (wid >> 1)*32;
    int nt = blockIdx.x, mt = blockIdx.y;
    const __nv_bfloat16 *Ah, *Al, *Bh, *Bl;
    int K, NITER, kc0, stride, b, sp = 0;
    if (MODE == 0) {
        b = blockIdx.z + bOff; K = Dc; NITER = 16; kc0 = 0; stride = 1;
        if (nt*128 >= g_kpad[b]) return;
        Ah = g_A1h + (size_t)b*HQc*Dc;  Al = g_A1l + (size_t)b*HQc*Dc;
        Bh = g_B1h + (size_t)b*Mc*Dc;   Bl = g_B1l + (size_t)b*Mc*Dc;
    } else {
        b = (blockIdx.z >> 3) + bOff; sp = blockIdx.z & 7; K = Mc;
        int ch = g_kpad[b] >> 5;
        NITER = (sp < ch) ? ((ch - sp + 7) >> 3) : 0;
        kc0 = sp; stride = 8;
        Ah = g_A2h + (size_t)b*HQc*Mc;  Al = g_A2l + (size_t)b*HQc*Mc;
        Bh = g_B2h + (size_t)b*Dc*Mc;   Bl = g_B2l + (size_t)b*Dc*Mc;
    }
    int m0 = mt*128, n0 = nt*128;

    float acc[4][4][4];
    #pragma unroll
    for (int i=0;i<4;i++)
        #pragma unroll
        for (int j=0;j<4;j++)
            #pragma unroll
            for (int e=0;e<4;e++) acc[i][j][e] = 0.f;

    #define LOAD_STAGE(ST, CI) do { \
        int kk_ = (kc0 + (CI)*stride)*32; \
        _Pragma("unroll") \
        for (int i_ = 0; i_ < 8; i_++) { \
            int c_ = tid + i_*256; \
            int tau_ = c_ >> 9, rem_ = c_ & 511, row_ = rem_ >> 2, ch_ = rem_ & 3; \
            uint32_t dst_ = sb + (ST)*STG + tau_*TILE_B + row_*TPAD + ch_*16; \
            const __nv_bfloat16* src_; \
            if (tau_ == 0)      src_ = Ah + (size_t)(m0+row_)*K + kk_ + ch_*8; \
            else if (tau_ == 1) src_ = Al + (size_t)(m0+row_)*K + kk_ + ch_*8; \
            else if (tau_ == 2) src_ = Bh + (size_t)(n0+row_)*K + kk_ + ch_*8; \
            else                src_ = Bl + (size_t)(n0+row_)*K + kk_ + ch_*8; \
            cp16(dst_, src_); \
        } \
        cp_commit(); \
    } while(0)

    if (NITER > 0) LOAD_STAGE(0, 0); else cp_commit();
    if (NITER > 1) LOAD_STAGE(1, 1); else cp_commit();

    int ra  = wm0 + (lane & 15);
    int ha  = (lane >> 4)*16;
    int rb  = wn0 + ((lane >> 4) << 3) + (lane & 7);
    int hb  = ((lane >> 3) & 1)*16;

    for (int ci = 0; ci < NITER; ci++) {
        cp_wait1();
        __syncthreads();
        int st = ci & 1;
        uint32_t Ahs = sb + st*STG;
        uint32_t Als = Ahs + TILE_B;
        uint32_t Bhs = Ahs + 2*TILE_B;
        uint32_t Bls = Ahs + 3*TILE_B;
        #pragma unroll
        for (int kk = 0; kk < 2; kk++) {
            uint32_t ah[4][4], al[4][4], bb[4][2];
            #pragma unroll
            for (int i = 0; i < 4; i++) {
                ldm4(ah[i], Ahs + (uint32_t)(ra + i*16)*TPAD + kk*32 + ha);
                ldm4(al[i], Als + (uint32_t)(ra + i*16)*TPAD + kk*32 + ha);
            }
            #pragma unroll
            for (int j2 = 0; j2 < 2; j2++) {
                uint32_t t4[4];
                ldm4(t4, Bhs + (uint32_t)(rb + j2*16)*TPAD + kk*32 + hb);
                bb[j2*2][0]=t4[0]; bb[j2*2][1]=t4[1]; bb[j2*2+1][0]=t4[2]; bb[j2*2+1][1]=t4[3];
            }
            #pragma unroll
            for (int i=0;i<4;i++)
                #pragma unroll
                for (int j=0;j<4;j++) mma16816(acc[i][j], ah[i], bb[j]);
            #pragma unroll
            for (int i=0;i<4;i++)
                #pragma unroll
                for (int j=0;j<4;j++) mma16816(acc[i][j], al[i], bb[j]);
            #pragma unroll
            for (int j2 = 0; j2 < 2; j2++) {
                uint32_t t4[4];
                ldm4(t4, Bls + (uint32_t)(rb + j2*16)*TPAD + kk*32 + hb);
                bb[j2*2][0]=t4[0]; bb[j2*2][1]=t4[1]; bb[j2*2+1][0]=t4[2]; bb[j2*2+1][1]=t4[3];
            }
            #pragma unroll
            for (int i=0;i<4;i++)
                #pragma unroll
                for (int j=0;j<4;j++) mma16816(acc[i][j], ah[i], bb[j]);
        }
        __syncthreads();
        if (ci + 2 < NITER) { LOAD_STAGE(st, ci + 2); } else { cp_commit(); }
    }

    int row4 = lane >> 2, col2 = (lane & 3)*2;
    #pragma unroll
    for (int i = 0; i < 4; i++) {
        #pragma unroll
        for (int rr = 0; rr < 2; rr++) {
            int r = m0 + wm0 + i*16 + row4 + rr*8;
            if (MODE == 0) {
                float kb = g_qkb[b*HQc + r];
                float* dst = g_attn + ((size_t)b*HQc + r)*Mc + n0 + wn0;
                #pragma unroll
                for (int j = 0; j < 4; j++) {
                    float2 v = make_float2(acc[i][j][rr*2] + kb, acc[i][j][rr*2+1] + kb);
                    *(float2*)(dst + j*8 + col2) = v;
                }
            } else {
                float* dst = g_ctxp[sp] + ((size_t)b*HQc + r)*Dc + n0 + wn0;
                #pragma unroll
                for (int j = 0; j < 4; j++) {
                    float2 v = make_float2(acc[i][j][rr*2], acc[i][j][rr*2+1]);
                    *(float2*)(dst + j*8 + col2) = v;
                }
            }
        }
    }
    #undef LOAD_STAGE
}

// ---------- fused softmax (compacted) + head-mean scatter + A2 emission ----------
__global__ __launch_bounds__(512) void k_softmax_mean(const int* __restrict__ mask,
                                                      float* __restrict__ out, int bOff) {
    int bid = blockIdx.x + bOff*Qc; int b = bid >> 5, q = bid & 31; int t = threadIdx.x;
    int lane = t & 31, wid = t >> 5;
    int cnt = g_cnt[b], kpad = g_kpad[b];
    __shared__ float red[16]; __shared__ float bcs[2];
    uint32_t mbits = 0;
    {
        const int4* mk = (const int4*)(mask + (size_t)b*Mc + t*16);
        #pragma unroll
        for (int i = 0; i < 4; i++) {
            int4 mm = mk[i];
            if (mm.x) mbits |= 1u << (i*4+0);
            if (mm.y) mbits |= 1u << (i*4+1);
            if (mm.z) mbits |= 1u << (i*4+2);
            if (mm.w) mbits |= 1u << (i*4+3);
        }
    }
    int j0 = t*16;
    float macc[16];
    #pragma unroll
    for (int i = 0; i < 16; i++) macc[i] = 0.f;

    for (int h = 0; h < Hc; h++) {
        size_t row = (size_t)b*HQc + h*Qc + q;
        const float4* rp = (const float4*)(g_attn + row*Mc + j0);
        float v[16];
        #pragma unroll
        for (int i = 0; i < 4; i++) {
            float4 x = rp[i];
            v[i*4+0] = (j0 + i*4 + 0 < cnt) ? x.x : -INFINITY;
            v[i*4+1] = (j0 + i*4 + 1 < cnt) ? x.y : -INFINITY;
            v[i*4+2] = (j0 + i*4 + 2 < cnt) ? x.z : -INFINITY;
            v[i*4+3] = (j0 + i*4 + 3 < cnt) ? x.w : -INFINITY;
        }
        float mx = -INFINITY;
        #pragma unroll
        for (int i = 0; i < 16; i++) mx = fmaxf(mx, v[i]);
        #pragma unroll
        for (int o = 16; o > 0; o >>= 1) mx = fmaxf(mx, __shfl_xor_sync(0xffffffffu, mx, o));
        if (lane == 0) red[wid] = mx;
        __syncthreads();
        if (t < 32) {
            float y = (lane < 16) ? red[lane] : -INFINITY;
            #pragma unroll
            for (int o = 8; o > 0; o >>= 1) y = fmaxf(y, __shfl_xor_sync(0xffffffffu, y, o));
            if (t == 0) bcs[0] = y;
        }
        __syncthreads();
        float rowmax = bcs[0];
        float s = 0.f;
        #pragma unroll
        for (int i = 0; i < 16; i++) { float e = __expf(v[i] - rowmax); v[i] = e; s += e; }
        #pragma unroll
        for (int o = 16; o > 0; o >>= 1) s += __shfl_xor_sync(0xffffffffu, s, o);
        if (lane == 0) red[wid] = s;
        __syncthreads();
        if (t < 32) {
            float y = (lane < 16) ? red[lane] : 0.f;
            #pragma unroll
            for (int o = 8; o > 0; o >>= 1) y += __shfl_xor_sync(0xffffffffu, y, o);
            if (t == 0) bcs[1] = 1.0f / y;
        }
        __syncthreads();
        float inv = bcs[1];
        #pragma unroll
        for (int i = 0; i < 16; i++) {
            v[i] = (j0 + i < cnt) ? v[i]*inv : 0.f;
            macc[i] += v[i];
        }
        if (j0 < kpad) {
            size_t abase = row*Mc + j0;
            uint4 h0, l0, h1, l1;
            cvt8(v, &h0, &l0); cvt8(v + 8, &h1, &l1);
            *(uint4*)(g_A2h + abase)     = h0;
            *(uint4*)(g_A2h + abase + 8) = h1;
            *(uint4*)(g_A2l + abase)     = l0;
            *(uint4*)(g_A2l + abase + 8) = l1;
        }
        __syncthreads();
    }
    float* orow = out + OFF_A + (size_t)bid*Mc;
    #pragma unroll
    for (int i = 0; i < 16; i++) {
        int o = j0 + i;
        if (!((mbits >> i) & 1)) orow[o] = 0.f;
    }
    #pragma unroll
    for (int i = 0; i < 16; i++) {
        int j = j0 + i;
        if (j < cnt) orow[g_midx[b][j]] = macc[i]*0.125f;
    }
}

// ---------- epilogue (half-batch) ----------
__global__ __launch_bounds__(256) void k_epilogue(const float* __restrict__ in_w,
        const float* __restrict__ in_b, const float* __restrict__ out_w,
        const float* __restrict__ out_b, const float* __restrict__ ln_g,
        const float* __restrict__ ln_b, float* __restrict__ out, int bOff) {
    int b = blockIdx.x + bOff, q = blockIdx.y, t = threadIdx.x;
    __shared__ __align__(16) float cm[Hc][Dc];
    __shared__ __align__(16) float co[Dc];
    __shared__ float rsum[8], rsq[8], bcs[2];
    #pragma unroll
    for (int j = 0; j < 16; j++) {
        int idx = t + j*256; int h = idx >> 9, e = idx & 511;
        size_t off = ((size_t)b*HQc + h*Qc + q)*Dc + e;
        float s = 0.f;
        #pragma unroll
        for (int sp = 0; sp < 8; sp++) s += g_ctxp[sp][off];
        cm[h][e] = s;
    }
    __syncthreads();
    for (int f = t; f < Dc; f += 256) {
        int h = f >> 6;
        const float4* w  = (const float4*)(in_w + (size_t)(2*Dc + f)*Dc);
        const float4* c4 = (const float4*)cm[h];
        float acc = in_b[2*Dc + f];
        #pragma unroll 8
        for (int e = 0; e < Dc/4; e++) {
            float4 wv = w[e], cv = c4[e];
            acc += wv.x*cv.x + wv.y*cv.y + wv.z*cv.z + wv.w*cv.w;
        }
        co[f] = acc;
    }
    __syncthreads();
    float g = out[OFF_G + b*Qc + q];
    const float4* co4 = (const float4*)co;
    float r[2];
    #pragma unroll
    for (int half = 0; half < 2; half++) {
        int d = t + half*256;
        const float4* w = (const float4*)(out_w + (size_t)d*Dc);
        float acc = out_b[d];
        #pragma unroll 8
        for (int e = 0; e < Dc/4; e++) {
            float4 wv = w[e], cv = co4[e];
            acc += wv.x*cv.x + wv.y*cv.y + wv.z*cv.z + wv.w*cv.w;
        }
        r[half] = acc * g;
    }
    float ssum = r[0] + r[1];
    float ssq  = r[0]*r[0] + r[1]*r[1];
    #pragma unroll
    for (int o = 16; o > 0; o >>= 1) {
        ssum += __shfl_xor_sync(0xffffffffu, ssum, o);
        ssq  += __shfl_xor_sync(0xffffffffu, ssq,  o);
    }
    if ((t & 31) == 0) { rsum[t >> 5] = ssum; rsq[t >> 5] = ssq; }
    __syncthreads();
    if (t == 0) {
        float S = 0.f, SQ = 0.f;
        #pragma unroll
        for (int i = 0; i < 8; i++) { S += rsum[i]; SQ += rsq[i]; }
        float mu = S * (1.0f/Dc);
        float var = SQ * (1.0f/Dc) - mu*mu;
        bcs[0] = mu; bcs[1] = rsqrtf(var + 1e-5f);
    }
    __syncthreads();
    float mu = bcs[0], rs = bcs[1];
    size_t obase = OFF_R + ((size_t)(b*Qc + q))*Dc;
    #pragma unroll
    for (int half = 0; half < 2; half++) {
        int d = t + half*256;
        out[obase + d] = (r[half] - mu)*rs*ln_g[d] + ln_b[d];
    }
}

// ---------- launch: two half-batch chains on two streams ----------
extern "C" void kernel_launch(void* const* d_in, const int* in_sizes, int n_in,
                              void* d_out, int out_size) {
    const float* memory  = (const float*)d_in[0];
    const float* context = (const float*)d_in[1];
    const int*   mask    = (const int*)d_in[2];
    const float* qp      = (const float*)d_in[3];
    const float* ctx_w   = (const float*)d_in[4];
    const float* ctx_b   = (const float*)d_in[5];
    const float* in_w    = (const float*)d_in[6];
    const float* in_b    = (const float*)d_in[7];
    const float* out_w   = (const float*)d_in[8];
    const float* out_b   = (const float*)d_in[9];
    const float* ln_g    = (const float*)d_in[10];
    const float* ln_b    = (const float*)d_in[11];
    const float* gate_w  = (const float*)d_in[12];
    const float* gate_b  = (const float*)d_in[13];
    float* out = (float*)d_out;

    static cudaStream_t s1 = nullptr;
    static cudaEvent_t evA, evQ, evC0, evE;
    if (!s1) {
        cudaStreamCreateWithFlags(&s1, cudaStreamNonBlocking);
        cudaEventCreateWithFlags(&evA,  cudaEventDisableTiming);
        cudaEventCreateWithFlags(&evQ,  cudaEventDisableTiming);
        cudaEventCreateWithFlags(&evC0, cudaEventDisableTiming);
        cudaEventCreateWithFlags(&evE,  cudaEventDisableTiming);
        cudaFuncSetAttribute(k_gemm<0>, cudaFuncAttributeMaxDynamicSharedMemorySize, GSMEM);
        cudaFuncSetAttribute(k_gemm<1>, cudaFuncAttributeMaxDynamicSharedMemorySize, GSMEM);
    }

    // fork
    cudaEventRecord(evA, 0);
    cudaStreamWaitEvent(s1, evA, 0);

    // s0: q-chain
    k_pooled      <<<Bc, Dc>>>(context);
    k_cq_gates    <<<Bc, Dc>>>(ctx_w, ctx_b, gate_w, gate_b, out);
    k_queries_qs  <<<Bc*Qc, 256>>>(qp, in_w, in_b, out);
    k_qk          <<<dim3(Hc, 16, 4), 128>>>(in_w);
    cudaEventRecord(evQ, 0);

    // s1: scan + convT halves
    k_mask_scan   <<<Bc, 1024, 0, s1>>>(mask);
    k_convT       <<<dim3(128, 4, 4), 256, 0, s1>>>(memory, 0);
    cudaEventRecord(evC0, s1);
    k_convT       <<<dim3(128, 4, 4), 256, 0, s1>>>(memory, 4);

    // s0 chain: batches 0-3 (needs convT(0-3))
    cudaStreamWaitEvent(0, evC0, 0);
    k_gemm<0>     <<<dim3(64, 2, 4), 256, GSMEM>>>(0);
    k_softmax_mean<<<4*Qc, 512>>>(mask, out, 0);
    k_gemm<1>     <<<dim3(4, 2, 32), 256, GSMEM>>>(0);
    k_epilogue    <<<dim3(4, Qc), 256>>>(in_w, in_b, out_w, out_b, ln_g, ln_b, out, 0);

    // s1 chain: batches 4-7 (needs q-chain; convT(4-7) already ordered on s1)
    cudaStreamWaitEvent(s1, evQ, 0);
    k_gemm<0>     <<<dim3(64, 2, 4), 256, GSMEM, s1>>>(4);
    k_softmax_mean<<<4*Qc, 512, 0, s1>>>(mask, out, 4);
    k_gemm<1>     <<<dim3(4, 2, 32), 256, GSMEM, s1>>>(4);
    k_epilogue    <<<dim3(4, Qc), 256, 0, s1>>>(in_w, in_b, out_w, out_b, ln_g, ln_b, out, 4);

    // join
    cudaEventRecord(evE, s1);
    cudaStreamWaitEvent(0, evE, 0);
}

// round 13
// speedup vs baseline: 1.3366x; 1.3366x over previous
#include <cuda_runtime.h>
#include <cuda_bf16.h>
#include <math.h>
#include <stdint.h>

#define Bc 8
#define Mc 8192
#define Sc 128
#define Dc 512
#define Qc 32
#define Hc 8
#define HDc 64
#define HQc 256

#define OFF_R 0
#define OFF_A (Bc*Qc*Dc)
#define OFF_G (OFF_A + Bc*Qc*Mc)
#define OFF_Q (OFF_G + Bc*Qc)

__device__ float g_pooled[Bc*Dc];
__device__ float g_cq[Bc*Dc];
__device__ float g_qs[Bc*Qc*Dc];
__device__ float g_qkb[Bc*HQc];
__device__ float g_attn[(size_t)Bc*HQc*Mc];          // compacted raw scores
__device__ float g_ctxp[4][(size_t)Bc*HQc*Dc];
__device__ int   g_midx[Bc][Mc];
__device__ int   g_cnt[Bc];
__device__ int   g_kpad[Bc];
__device__ __align__(16) __nv_bfloat16 g_A1h[(size_t)Bc*HQc*Dc];
__device__ __align__(16) __nv_bfloat16 g_A1l[(size_t)Bc*HQc*Dc];
__device__ __align__(16) __nv_bfloat16 g_B1h[(size_t)Bc*Mc*Dc];    // compacted memory rows
__device__ __align__(16) __nv_bfloat16 g_B1l[(size_t)Bc*Mc*Dc];
__device__ __align__(16) __nv_bfloat16 g_A2h[(size_t)Bc*HQc*Mc];   // compacted attn
__device__ __align__(16) __nv_bfloat16 g_A2l[(size_t)Bc*HQc*Mc];
__device__ __align__(16) __nv_bfloat16 g_B2h[(size_t)Bc*Dc*Mc];    // compacted memory^T
__device__ __align__(16) __nv_bfloat16 g_B2l[(size_t)Bc*Dc*Mc];

__device__ __forceinline__ void cvt8(const float* v, uint4* hi, uint4* lo){
    union { uint4 u; __nv_bfloat16 h[8]; } a, b;
    #pragma unroll
    for (int j=0;j<8;j++){
        float x = v[j];
        __nv_bfloat16 h = __float2bfloat16(x);
        a.h[j] = h;
        b.h[j] = __float2bfloat16(x - __bfloat162float(h));
    }
    *hi = a.u; *lo = b.u;
}
__device__ __forceinline__ uint32_t smem_u32(const void* p){
    uint32_t a;
    asm("{ .reg .u64 t; cvta.to.shared.u64 t, %1; cvt.u32.u64 %0, t; }" : "=r"(a) : "l"(p));
    return a;
}
__device__ __forceinline__ void cp16(uint32_t dst, const void* src){
    asm volatile("cp.async.cg.shared.global [%0], [%1], 16;" :: "r"(dst), "l"(src));
}
__device__ __forceinline__ void cp_commit(){ asm volatile("cp.async.commit_group;" ::: "memory"); }
__device__ __forceinline__ void cp_wait1(){ asm volatile("cp.async.wait_group 1;" ::: "memory"); }
__device__ __forceinline__ void ldm4(uint32_t* r, uint32_t a){
    asm volatile("ldmatrix.sync.aligned.m8n8.x4.shared.b16 {%0,%1,%2,%3}, [%4];"
      : "=r"(r[0]),"=r"(r[1]),"=r"(r[2]),"=r"(r[3]) : "r"(a));
}
__device__ __forceinline__ void mma16816(float* c, const uint32_t* a, const uint32_t* b){
    asm volatile("mma.sync.aligned.m16n8k16.row.col.f32.bf16.bf16.f32 "
      "{%0,%1,%2,%3}, {%4,%5,%6,%7}, {%8,%9}, {%0,%1,%2,%3};"
      : "+f"(c[0]),"+f"(c[1]),"+f"(c[2]),"+f"(c[3])
      : "r"(a[0]),"r"(a[1]),"r"(a[2]),"r"(a[3]), "r"(b[0]),"r"(b[1]));
}

// ---------- mask prefix-scan ----------
__global__ __launch_bounds__(1024) void k_mask_scan(const int* __restrict__ mask){
    int b = blockIdx.x, t = threadIdx.x;
    __shared__ int wsum[32];
    for (int j = t; j < Mc; j += 1024) g_midx[b][j] = 0;
    __syncthreads();
    int bits[8]; int loc = 0;
    #pragma unroll
    for (int i = 0; i < 8; i++) { bits[i] = (mask[(size_t)b*Mc + t*8 + i] != 0); loc += bits[i]; }
    int lane = t & 31, w = t >> 5;
    int x = loc;
    #pragma unroll
    for (int o = 1; o < 32; o <<= 1) { int y = __shfl_up_sync(0xffffffffu, x, o); if (lane >= o) x += y; }
    if (lane == 31) wsum[w] = x;
    __syncthreads();
    if (t < 32) {
        int y = wsum[t];
        #pragma unroll
        for (int o = 1; o < 32; o <<= 1) { int z = __shfl_up_sync(0xffffffffu, y, o); if (t >= o) y += z; }
        wsum[t] = y;
    }
    __syncthreads();
    int base = x - loc + (w ? wsum[w-1] : 0);
    #pragma unroll
    for (int i = 0; i < 8; i++) if (bits[i]) g_midx[b][base++] = t*8 + i;
    if (t == 0) { int cnt = wsum[31]; g_cnt[b] = cnt; g_kpad[b] = ((cnt + 127) >> 7) << 7; }
}

// ---------- small kernels ----------
__global__ void k_pooled(const float* __restrict__ ctx) {
    int b = blockIdx.x, d = threadIdx.x;
    const float* p = ctx + (size_t)b*Sc*Dc + d;
    float s = 0.f;
    #pragma unroll 8
    for (int i = 0; i < Sc; i++) s += p[(size_t)i*Dc];
    g_pooled[b*Dc + d] = s * (1.0f/Sc);
}
__global__ void k_cq_gates(const float* __restrict__ ctx_w, const float* __restrict__ ctx_b,
                           const float* __restrict__ gate_w, const float* __restrict__ gate_b,
                           float* __restrict__ out) {
    int b = blockIdx.x, t = threadIdx.x;
    __shared__ __align__(16) float pool[Dc];
    pool[t] = g_pooled[b*Dc + t];
    __syncthreads();
    const float4* p4 = (const float4*)pool;
    const float4* w = (const float4*)(ctx_w + (size_t)t*Dc);
    float acc = ctx_b[t];
    #pragma unroll 8
    for (int e = 0; e < Dc/4; e++) {
        float4 wv = w[e], pv = p4[e];
        acc += wv.x*pv.x + wv.y*pv.y + wv.z*pv.z + wv.w*pv.w;
    }
    g_cq[b*Dc + t] = acc;
    if (t < Qc) {
        const float4* gw = (const float4*)(gate_w + (size_t)t*Dc);
        float a2 = gate_b[t];
        #pragma unroll 8
        for (int e = 0; e < Dc/4; e++) {
            float4 wv = gw[e], pv = p4[e];
            a2 += wv.x*pv.x + wv.y*pv.y + wv.z*pv.z + wv.w*pv.w;
        }
        out[OFF_G + b*Qc + t] = 1.0f/(1.0f + expf(-a2));
    }
}
__global__ void k_queries_qs(const float* __restrict__ qp, const float* __restrict__ in_w,
                             const float* __restrict__ in_b, float* __restrict__ out) {
    int bid = blockIdx.x; int b = bid >> 5, q = bid & 31; int t = threadIdx.x;
    __shared__ __align__(16) float qrow[Dc];
    __shared__ __align__(16) float qs_s[Dc];
    for (int i = t; i < Dc; i += 256) {
        float v = qp[q*Dc + i] + g_cq[b*Dc + i];
        qrow[i] = v;
        out[OFF_Q + (size_t)bid*Dc + i] = v;
    }
    __syncthreads();
    const float4* q4 = (const float4*)qrow;
    for (int f = t; f < Dc; f += 256) {
        const float4* w = (const float4*)(in_w + (size_t)f*Dc);
        float acc = in_b[f];
        #pragma unroll 8
        for (int e = 0; e < Dc/4; e++) {
            float4 wv = w[e], pv = q4[e];
            acc += wv.x*pv.x + wv.y*pv.y + wv.z*pv.z + wv.w*pv.w;
        }
        float v = acc * 0.125f;
        qs_s[f] = v;
        g_qs[(size_t)bid*Dc + f] = v;
    }
    __syncthreads();
    if (t < Hc) {
        float s = 0.f;
        #pragma unroll
        for (int hd = 0; hd < HDc; hd++) s += qs_s[t*HDc + hd] * in_b[Dc + t*HDc + hd];
        g_qkb[b*HQc + t*Qc + q] = s;
    }
}
// 8-row blocks (1024 total) for latency hiding
__global__ __launch_bounds__(128) void k_qk(const float* __restrict__ in_w) {
    int h = blockIdx.x, r0 = blockIdx.y*8, t = threadIdx.x;
    int c = blockIdx.z*128 + t;
    __shared__ float A[8][65];
    for (int j = t; j < 8*64; j += 128) A[j>>6][j&63] = g_qs[(size_t)(r0 + (j>>6))*Dc + h*HDc + (j&63)];
    __syncthreads();
    float acc[8];
    #pragma unroll
    for (int r = 0; r < 8; r++) acc[r] = 0.f;
    const float* wk = in_w + (size_t)(Dc + h*HDc)*Dc;
    #pragma unroll 8
    for (int hd = 0; hd < HDc; hd++) {
        float w = wk[(size_t)hd*Dc + c];
        #pragma unroll
        for (int r = 0; r < 8; r++) acc[r] += A[r][hd]*w;
    }
    #pragma unroll
    for (int r = 0; r < 8; r++) {
        int bq = r0 + r; int b = bq >> 5, q = bq & 31;
        size_t idx = ((size_t)b*HQc + h*Qc + q)*Dc + c;
        float x = acc[r];
        __nv_bfloat16 hi = __float2bfloat16(x);
        g_A1h[idx] = hi;
        g_A1l[idx] = __float2bfloat16(x - __bfloat162float(hi));
    }
}

// ---------- gathered conversion: compacted B1 (K-major) + B2 (transposed) ----------
__global__ __launch_bounds__(256) void k_convT(const float* __restrict__ mem) {
    int mb = blockIdx.x, db = blockIdx.y, b = blockIdx.z, t = threadIdx.x;
    int m0 = mb*64;
    if (m0 >= g_kpad[b]) return;
    int cnt = g_cnt[b];
    __shared__ int sidx[64];
    __shared__ float s[64][129];
    if (t < 64) { int j = m0 + t; sidx[t] = (j < cnt) ? g_midx[b][j] : 0; }
    __syncthreads();
    int d0 = db*128;
    for (int it = 0; it < 8; it++) {
        int idx = t + it*256; int r = idx >> 5, c4 = idx & 31;
        float4 v = *(const float4*)(mem + ((size_t)b*Mc + sidx[r])*Dc + d0 + c4*4);
        s[r][c4*4+0] = v.x; s[r][c4*4+1] = v.y; s[r][c4*4+2] = v.z; s[r][c4*4+3] = v.w;
    }
    __syncthreads();
    {
        int r = t >> 2, ds = (t & 3)*32;
        size_t base = ((size_t)b*Mc + m0 + r)*Dc + d0 + ds;
        #pragma unroll
        for (int g = 0; g < 4; g++) {
            float v[8];
            #pragma unroll
            for (int j = 0; j < 8; j++) v[j] = s[r][ds + g*8 + j];
            uint4 hi, lo; cvt8(v, &hi, &lo);
            *(uint4*)(g_B1h + base + g*8) = hi;
            *(uint4*)(g_B1l + base + g*8) = lo;
        }
    }
    for (int it = 0; it < 2; it++) {
        int u = t + it*256; int dl = u >> 2, g = u & 3;
        float v[16];
        #pragma unroll
        for (int j = 0; j < 16; j++) v[j] = s[g*16 + j][dl];
        uint4 h0, l0, h1, l1;
        cvt8(v, &h0, &l0); cvt8(v + 8, &h1, &l1);
        size_t base = ((size_t)b*Dc + d0 + dl)*Mc + m0 + g*16;
        *(uint4*)(g_B2h + base)     = h0;
        *(uint4*)(g_B2h + base + 8) = h1;
        *(uint4*)(g_B2l + base)     = l0;
        *(uint4*)(g_B2l + base + 8) = l1;
    }
}

// ---------- HMMA GEMM (NT), 128x128 tile, BK=32, bf16 split-3, full-batch ----------
#define TPAD 80
#define TILE_B 10240
#define STG   40960
#define GSMEM (2*STG)
template<int MODE>
__global__ __launch_bounds__(256, 1) void k_gemm() {
    extern __shared__ __align__(128) unsigned char smraw[];
    uint32_t sb = smem_u32(smraw);
    int tid = threadIdx.x, lane = tid & 31, wid = tid >> 5;
    int wm0 = (wid & 1)*64, wn0 = (wid >> 1)*32;
    int nt = blockIdx.x, mt = blockIdx.y;
    const __nv_bfloat16 *Ah, *Al, *Bh, *Bl;
    int K, NITER, kc0, stride, b, sp = 0;
    if (MODE == 0) {
        b = blockIdx.z; K = Dc; NITER = 16; kc0 = 0; stride = 1;
        if (nt*128 >= g_kpad[b]) return;
        Ah = g_A1h + (size_t)b*HQc*Dc;  Al = g_A1l + (size_t)b*HQc*Dc;
        Bh = g_B1h + (size_t)b*Mc*Dc;   Bl = g_B1l + (size_t)b*Mc*Dc;
    } else {
        b = blockIdx.z >> 2; sp = blockIdx.z & 3; K = Mc;
        int ch = g_kpad[b] >> 5;
        NITER = (sp < ch) ? ((ch - sp + 3) >> 2) : 0;
        kc0 = sp; stride = 4;
        Ah = g_A2h + (size_t)b*HQc*Mc;  Al = g_A2l + (size_t)b*HQc*Mc;
        Bh = g_B2h + (size_t)b*Dc*Mc;   Bl = g_B2l + (size_t)b*Dc*Mc;
    }
    int m0 = mt*128, n0 = nt*128;

    float acc[4][4][4];
    #pragma unroll
    for (int i=0;i<4;i++)
        #pragma unroll
        for (int j=0;j<4;j++)
            #pragma unroll
            for (int e=0;e<4;e++) acc[i][j][e] = 0.f;

    #define LOAD_STAGE(ST, CI) do { \
        int kk_ = (kc0 + (CI)*stride)*32; \
        _Pragma("unroll") \
        for (int i_ = 0; i_ < 8; i_++) { \
            int c_ = tid + i_*256; \
            int tau_ = c_ >> 9, rem_ = c_ & 511, row_ = rem_ >> 2, ch_ = rem_ & 3; \
            uint32_t dst_ = sb + (ST)*STG + tau_*TILE_B + row_*TPAD + ch_*16; \
            const __nv_bfloat16* src_; \
            if (tau_ == 0)      src_ = Ah + (size_t)(m0+row_)*K + kk_ + ch_*8; \
            else if (tau_ == 1) src_ = Al + (size_t)(m0+row_)*K + kk_ + ch_*8; \
            else if (tau_ == 2) src_ = Bh + (size_t)(n0+row_)*K + kk_ + ch_*8; \
            else                src_ = Bl + (size_t)(n0+row_)*K + kk_ + ch_*8; \
            cp16(dst_, src_); \
        } \
        cp_commit(); \
    } while(0)

    if (NITER > 0) LOAD_STAGE(0, 0); else cp_commit();
    if (NITER > 1) LOAD_STAGE(1, 1); else cp_commit();

    int ra  = wm0 + (lane & 15);
    int ha  = (lane >> 4)*16;
    int rb  = wn0 + ((lane >> 4) << 3) + (lane & 7);
    int hb  = ((lane >> 3) & 1)*16;

    for (int ci = 0; ci < NITER; ci++) {
        cp_wait1();
        __syncthreads();
        int st = ci & 1;
        uint32_t Ahs = sb + st*STG;
        uint32_t Als = Ahs + TILE_B;
        uint32_t Bhs = Ahs + 2*TILE_B;
        uint32_t Bls = Ahs + 3*TILE_B;
        #pragma unroll
        for (int kk = 0; kk < 2; kk++) {
            uint32_t ah[4][4], al[4][4], bb[4][2];
            #pragma unroll
            for (int i = 0; i < 4; i++) {
                ldm4(ah[i], Ahs + (uint32_t)(ra + i*16)*TPAD + kk*32 + ha);
                ldm4(al[i], Als + (uint32_t)(ra + i*16)*TPAD + kk*32 + ha);
            }
            #pragma unroll
            for (int j2 = 0; j2 < 2; j2++) {
                uint32_t t4[4];
                ldm4(t4, Bhs + (uint32_t)(rb + j2*16)*TPAD + kk*32 + hb);
                bb[j2*2][0]=t4[0]; bb[j2*2][1]=t4[1]; bb[j2*2+1][0]=t4[2]; bb[j2*2+1][1]=t4[3];
            }
            #pragma unroll
            for (int i=0;i<4;i++)
                #pragma unroll
                for (int j=0;j<4;j++) mma16816(acc[i][j], ah[i], bb[j]);
            #pragma unroll
            for (int i=0;i<4;i++)
                #pragma unroll
                for (int j=0;j<4;j++) mma16816(acc[i][j], al[i], bb[j]);
            #pragma unroll
            for (int j2 = 0; j2 < 2; j2++) {
                uint32_t t4[4];
                ldm4(t4, Bls + (uint32_t)(rb + j2*16)*TPAD + kk*32 + hb);
                bb[j2*2][0]=t4[0]; bb[j2*2][1]=t4[1]; bb[j2*2+1][0]=t4[2]; bb[j2*2+1][1]=t4[3];
            }
            #pragma unroll
            for (int i=0;i<4;i++)
                #pragma unroll
                for (int j=0;j<4;j++) mma16816(acc[i][j], ah[i], bb[j]);
        }
        __syncthreads();
        if (ci + 2 < NITER) { LOAD_STAGE(st, ci + 2); } else { cp_commit(); }
    }

    int row4 = lane >> 2, col2 = (lane & 3)*2;
    #pragma unroll
    for (int i = 0; i < 4; i++) {
        #pragma unroll
        for (int rr = 0; rr < 2; rr++) {
            int r = m0 + wm0 + i*16 + row4 + rr*8;
            if (MODE == 0) {
                float kb = g_qkb[b*HQc + r];
                float* dst = g_attn + ((size_t)b*HQc + r)*Mc + n0 + wn0;
                #pragma unroll
                for (int j = 0; j < 4; j++) {
                    float2 v = make_float2(acc[i][j][rr*2] + kb, acc[i][j][rr*2+1] + kb);
                    *(float2*)(dst + j*8 + col2) = v;
                }
            } else {
                float* dst = g_ctxp[sp] + ((size_t)b*HQc + r)*Dc + n0 + wn0;
                #pragma unroll
                for (int j = 0; j < 4; j++) {
                    float2 v = make_float2(acc[i][j][rr*2], acc[i][j][rr*2+1]);
                    *(float2*)(dst + j*8 + col2) = v;
                }
            }
        }
    }
    #undef LOAD_STAGE
}

// ---------- fused softmax (compacted, kpad-bounded) + head-mean scatter + A2 ----------
__global__ __launch_bounds__(512) void k_softmax_mean(const int* __restrict__ mask,
                                                      float* __restrict__ out) {
    int bid = blockIdx.x; int b = bid >> 5, q = bid & 31; int t = threadIdx.x;
    int lane = t & 31, wid = t >> 5;
    int cnt = g_cnt[b], kpad = g_kpad[b];
    __shared__ float red[16]; __shared__ float bcs[2];
    uint32_t mbits = 0;
    {
        const int4* mk = (const int4*)(mask + (size_t)b*Mc + t*16);
        #pragma unroll
        for (int i = 0; i < 4; i++) {
            int4 mm = mk[i];
            if (mm.x) mbits |= 1u << (i*4+0);
            if (mm.y) mbits |= 1u << (i*4+1);
            if (mm.z) mbits |= 1u << (i*4+2);
            if (mm.w) mbits |= 1u << (i*4+3);
        }
    }
    int j0 = t*16;
    bool active = j0 < kpad;
    float macc[16];
    #pragma unroll
    for (int i = 0; i < 16; i++) macc[i] = 0.f;

    for (int h = 0; h < Hc; h++) {
        size_t row = (size_t)b*HQc + h*Qc + q;
        const float4* rp = (const float4*)(g_attn + row*Mc + j0);
        float v[16];
        if (active) {
            #pragma unroll
            for (int i = 0; i < 4; i++) {
                float4 x = rp[i];
                v[i*4+0] = (j0 + i*4 + 0 < cnt) ? x.x : -INFINITY;
                v[i*4+1] = (j0 + i*4 + 1 < cnt) ? x.y : -INFINITY;
                v[i*4+2] = (j0 + i*4 + 2 < cnt) ? x.z : -INFINITY;
                v[i*4+3] = (j0 + i*4 + 3 < cnt) ? x.w : -INFINITY;
            }
        } else {
            #pragma unroll
            for (int i = 0; i < 16; i++) v[i] = -INFINITY;
        }
        float mx = -INFINITY;
        #pragma unroll
        for (int i = 0; i < 16; i++) mx = fmaxf(mx, v[i]);
        #pragma unroll
        for (int o = 16; o > 0; o >>= 1) mx = fmaxf(mx, __shfl_xor_sync(0xffffffffu, mx, o));
        if (lane == 0) red[wid] = mx;
        __syncthreads();
        if (t < 32) {
            float y = (lane < 16) ? red[lane] : -INFINITY;
            #pragma unroll
            for (int o = 8; o > 0; o >>= 1) y = fmaxf(y, __shfl_xor_sync(0xffffffffu, y, o));
            if (t == 0) bcs[0] = y;
        }
        __syncthreads();
        float rowmax = bcs[0];
        float s = 0.f;
        #pragma unroll
        for (int i = 0; i < 16; i++) { float e = __expf(v[i] - rowmax); v[i] = e; s += e; }
        #pragma unroll
        for (int o = 16; o > 0; o >>= 1) s += __shfl_xor_sync(0xffffffffu, s, o);
        if (lane == 0) red[wid] = s;
        __syncthreads();
        if (t < 32) {
            float y = (lane < 16) ? red[lane] : 0.f;
            #pragma unroll
            for (int o = 8; o > 0; o >>= 1) y += __shfl_xor_sync(0xffffffffu, y, o);
            if (t == 0) bcs[1] = 1.0f / y;
        }
        __syncthreads();
        float inv = bcs[1];
        #pragma unroll
        for (int i = 0; i < 16; i++) {
            v[i] = (j0 + i < cnt) ? v[i]*inv : 0.f;
            macc[i] += v[i];
        }
        if (active) {
            size_t abase = row*Mc + j0;
            uint4 h0, l0, h1, l1;
            cvt8(v, &h0, &l0); cvt8(v + 8, &h1, &l1);
            *(uint4*)(g_A2h + abase)     = h0;
            *(uint4*)(g_A2h + abase + 8) = h1;
            *(uint4*)(g_A2l + abase)     = l0;
            *(uint4*)(g_A2l + abase + 8) = l1;
        }
        __syncthreads();
    }
    float* orow = out + OFF_A + (size_t)bid*Mc;
    #pragma unroll
    for (int i = 0; i < 16; i++) {
        int o = j0 + i;
        if (!((mbits >> i) & 1)) orow[o] = 0.f;
    }
    #pragma unroll
    for (int i = 0; i < 16; i++) {
        int j = j0 + i;
        if (j < cnt) orow[g_midx[b][j]] = macc[i]*0.125f;
    }
}

// ---------- epilogue (full-batch, 4 split-K partials) ----------
__global__ __launch_bounds__(256) void k_epilogue(const float* __restrict__ in_w,
        const float* __restrict__ in_b, const float* __restrict__ out_w,
        const float* __restrict__ out_b, const float* __restrict__ ln_g,
        const float* __restrict__ ln_b, float* __restrict__ out) {
    int b = blockIdx.x, q = blockIdx.y, t = threadIdx.x;
    __shared__ __align__(16) float cm[Hc][Dc];
    __shared__ __align__(16) float co[Dc];
    __shared__ float rsum[8], rsq[8], bcs[2];
    #pragma unroll
    for (int j = 0; j < 16; j++) {
        int idx = t + j*256; int h = idx >> 9, e = idx & 511;
        size_t off = ((size_t)b*HQc + h*Qc + q)*Dc + e;
        float s = 0.f;
        #pragma unroll
        for (int sp = 0; sp < 4; sp++) s += g_ctxp[sp][off];
        cm[h][e] = s;
    }
    __syncthreads();
    for (int f = t; f < Dc; f += 256) {
        int h = f >> 6;
        const float4* w  = (const float4*)(in_w + (size_t)(2*Dc + f)*Dc);
        const float4* c4 = (const float4*)cm[h];
        float acc = in_b[2*Dc + f];
        #pragma unroll 8
        for (int e = 0; e < Dc/4; e++) {
            float4 wv = w[e], cv = c4[e];
            acc += wv.x*cv.x + wv.y*cv.y + wv.z*cv.z + wv.w*cv.w;
        }
        co[f] = acc;
    }
    __syncthreads();
    float g = out[OFF_G + b*Qc + q];
    const float4* co4 = (const float4*)co;
    float r[2];
    #pragma unroll
    for (int half = 0; half < 2; half++) {
        int d = t + half*256;
        const float4* w = (const float4*)(out_w + (size_t)d*Dc);
        float acc = out_b[d];
        #pragma unroll 8
        for (int e = 0; e < Dc/4; e++) {
            float4 wv = w[e], cv = co4[e];
            acc += wv.x*cv.x + wv.y*cv.y + wv.z*cv.z + wv.w*cv.w;
        }
        r[half] = acc * g;
    }
    float ssum = r[0] + r[1];
    float ssq  = r[0]*r[0] + r[1]*r[1];
    #pragma unroll
    for (int o = 16; o > 0; o >>= 1) {
        ssum += __shfl_xor_sync(0xffffffffu, ssum, o);
        ssq  += __shfl_xor_sync(0xffffffffu, ssq,  o);
    }
    if ((t & 31) == 0) { rsum[t >> 5] = ssum; rsq[t >> 5] = ssq; }
    __syncthreads();
    if (t == 0) {
        float S = 0.f, SQ = 0.f;
        #pragma unroll
        for (int i = 0; i < 8; i++) { S += rsum[i]; SQ += rsq[i]; }
        float mu = S * (1.0f/Dc);
        float var = SQ * (1.0f/Dc) - mu*mu;
        bcs[0] = mu; bcs[1] = rsqrtf(var + 1e-5f);
    }
    __syncthreads();
    float mu = bcs[0], rs = bcs[1];
    size_t obase = OFF_R + ((size_t)(b*Qc + q))*Dc;
    #pragma unroll
    for (int half = 0; half < 2; half++) {
        int d = t + half*256;
        out[obase + d] = (r[half] - mu)*rs*ln_g[d] + ln_b[d];
    }
}

// ---------- launch: R11 schedule (single-stream main chain + convT fork) ----------
extern "C" void kernel_launch(void* const* d_in, const int* in_sizes, int n_in,
                              void* d_out, int out_size) {
    const float* memory  = (const float*)d_in[0];
    const float* context = (const float*)d_in[1];
    const int*   mask    = (const int*)d_in[2];
    const float* qp      = (const float*)d_in[3];
    const float* ctx_w   = (const float*)d_in[4];
    const float* ctx_b   = (const float*)d_in[5];
    const float* in_w    = (const float*)d_in[6];
    const float* in_b    = (const float*)d_in[7];
    const float* out_w   = (const float*)d_in[8];
    const float* out_b   = (const float*)d_in[9];
    const float* ln_g    = (const float*)d_in[10];
    const float* ln_b    = (const float*)d_in[11];
    const float* gate_w  = (const float*)d_in[12];
    const float* gate_b  = (const float*)d_in[13];
    float* out = (float*)d_out;

    static cudaStream_t s1 = nullptr;
    static cudaEvent_t evA, evC;
    if (!s1) {
        cudaStreamCreateWithFlags(&s1, cudaStreamNonBlocking);
        cudaEventCreateWithFlags(&evA, cudaEventDisableTiming);
        cudaEventCreateWithFlags(&evC, cudaEventDisableTiming);
        cudaFuncSetAttribute(k_gemm<0>, cudaFuncAttributeMaxDynamicSharedMemorySize, GSMEM);
        cudaFuncSetAttribute(k_gemm<1>, cudaFuncAttributeMaxDynamicSharedMemorySize, GSMEM);
    }

    // fork: mask scan + gathered conversion concurrent with q-chain
    cudaEventRecord(evA, 0);
    cudaStreamWaitEvent(s1, evA, 0);

    k_pooled      <<<Bc, Dc>>>(context);
    k_cq_gates    <<<Bc, Dc>>>(ctx_w, ctx_b, gate_w, gate_b, out);
    k_queries_qs  <<<Bc*Qc, 256>>>(qp, in_w, in_b, out);
    k_qk          <<<dim3(Hc, 32, 4), 128>>>(in_w);

    k_mask_scan   <<<Bc, 1024, 0, s1>>>(mask);
    k_convT       <<<dim3(128, 4, Bc), 256, 0, s1>>>(memory);
    cudaEventRecord(evC, s1);
    cudaStreamWaitEvent(0, evC, 0);

    k_gemm<0>     <<<dim3(64, 2, Bc), 256, GSMEM>>>();
    k_softmax_mean<<<Bc*Qc, 512>>>(mask, out);
    k_gemm<1>     <<<dim3(4, 2, Bc*4), 256, GSMEM>>>();
    k_epilogue    <<<dim3(Bc, Qc), 256>>>(in_w, in_b, out_w, out_b, ln_g, ln_b, out);
}

// round 14
// speedup vs baseline: 1.5916x; 1.1907x over previous
#include <cuda_runtime.h>
#include <cuda_fp16.h>
#include <math.h>
#include <stdint.h>

#define Bc 8
#define Mc 8192
#define Sc 128
#define Dc 512
#define Qc 32
#define Hc 8
#define HDc 64
#define HQc 256

#define OFF_R 0
#define OFF_A (Bc*Qc*Dc)
#define OFF_G (OFF_A + Bc*Qc*Mc)
#define OFF_Q (OFF_G + Bc*Qc)

__device__ float g_pooled[Bc*Dc];
__device__ float g_cq[Bc*Dc];
__device__ float g_qs[Bc*Qc*Dc];
__device__ float g_qkb[Bc*HQc];
__device__ float g_attn[(size_t)Bc*HQc*Mc];          // compacted raw scores
__device__ float g_ctxp[4][(size_t)Bc*HQc*Dc];
__device__ int   g_midx[Bc][Mc];
__device__ int   g_cnt[Bc];
__device__ int   g_kpad[Bc];
__device__ __align__(16) __half g_A1[(size_t)Bc*HQc*Dc];      // qk fp16
__device__ __align__(16) __half g_B1[(size_t)Bc*Mc*Dc];       // compacted memory fp16
__device__ __align__(16) __half g_A2[(size_t)Bc*HQc*Mc];      // compacted attn fp16
__device__ __align__(16) __half g_B2h[(size_t)Bc*Dc*Mc];      // compacted memory^T hi
__device__ __align__(16) __half g_B2l[(size_t)Bc*Dc*Mc];      // residual lo

__device__ __forceinline__ void cvt8h(const float* v, uint4* o){
    union { uint4 u; __half h[8]; } a;
    #pragma unroll
    for (int j=0;j<8;j++) a.h[j] = __float2half_rn(v[j]);
    *o = a.u;
}
__device__ __forceinline__ void cvt8hs(const float* v, uint4* hi, uint4* lo){
    union { uint4 u; __half h[8]; } a, b;
    #pragma unroll
    for (int j=0;j<8;j++){
        float x = v[j];
        __half h = __float2half_rn(x);
        a.h[j] = h;
        b.h[j] = __float2half_rn(x - __half2float(h));
    }
    *hi = a.u; *lo = b.u;
}
__device__ __forceinline__ uint32_t smem_u32(const void* p){
    uint32_t a;
    asm("{ .reg .u64 t; cvta.to.shared.u64 t, %1; cvt.u32.u64 %0, t; }" : "=r"(a) : "l"(p));
    return a;
}
__device__ __forceinline__ void cp16(uint32_t dst, const void* src){
    asm volatile("cp.async.cg.shared.global [%0], [%1], 16;" :: "r"(dst), "l"(src));
}
__device__ __forceinline__ void cp_commit(){ asm volatile("cp.async.commit_group;" ::: "memory"); }
__device__ __forceinline__ void cp_wait1(){ asm volatile("cp.async.wait_group 1;" ::: "memory"); }
__device__ __forceinline__ void ldm4(uint32_t* r, uint32_t a){
    asm volatile("ldmatrix.sync.aligned.m8n8.x4.shared.b16 {%0,%1,%2,%3}, [%4];"
      : "=r"(r[0]),"=r"(r[1]),"=r"(r[2]),"=r"(r[3]) : "r"(a));
}
__device__ __forceinline__ void mma16816(float* c, const uint32_t* a, const uint32_t* b){
    asm volatile("mma.sync.aligned.m16n8k16.row.col.f32.f16.f16.f32 "
      "{%0,%1,%2,%3}, {%4,%5,%6,%7}, {%8,%9}, {%0,%1,%2,%3};"
      : "+f"(c[0]),"+f"(c[1]),"+f"(c[2]),"+f"(c[3])
      : "r"(a[0]),"r"(a[1]),"r"(a[2]),"r"(a[3]), "r"(b[0]),"r"(b[1]));
}

// ---------- mask prefix-scan ----------
__global__ __launch_bounds__(1024) void k_mask_scan(const int* __restrict__ mask){
    int b = blockIdx.x, t = threadIdx.x;
    __shared__ int wsum[32];
    for (int j = t; j < Mc; j += 1024) g_midx[b][j] = 0;
    __syncthreads();
    int bits[8]; int loc = 0;
    #pragma unroll
    for (int i = 0; i < 8; i++) { bits[i] = (mask[(size_t)b*Mc + t*8 + i] != 0); loc += bits[i]; }
    int lane = t & 31, w = t >> 5;
    int x = loc;
    #pragma unroll
    for (int o = 1; o < 32; o <<= 1) { int y = __shfl_up_sync(0xffffffffu, x, o); if (lane >= o) x += y; }
    if (lane == 31) wsum[w] = x;
    __syncthreads();
    if (t < 32) {
        int y = wsum[t];
        #pragma unroll
        for (int o = 1; o < 32; o <<= 1) { int z = __shfl_up_sync(0xffffffffu, y, o); if (t >= o) y += z; }
        wsum[t] = y;
    }
    __syncthreads();
    int base = x - loc + (w ? wsum[w-1] : 0);
    #pragma unroll
    for (int i = 0; i < 8; i++) if (bits[i]) g_midx[b][base++] = t*8 + i;
    if (t == 0) { int cnt = wsum[31]; g_cnt[b] = cnt; g_kpad[b] = ((cnt + 127) >> 7) << 7; }
}

// ---------- small kernels ----------
__global__ void k_pooled(const float* __restrict__ ctx) {
    int b = blockIdx.x, d = threadIdx.x;
    const float* p = ctx + (size_t)b*Sc*Dc + d;
    float s = 0.f;
    #pragma unroll 8
    for (int i = 0; i < Sc; i++) s += p[(size_t)i*Dc];
    g_pooled[b*Dc + d] = s * (1.0f/Sc);
}
__global__ void k_cq_gates(const float* __restrict__ ctx_w, const float* __restrict__ ctx_b,
                           const float* __restrict__ gate_w, const float* __restrict__ gate_b,
                           float* __restrict__ out) {
    int b = blockIdx.x, t = threadIdx.x;
    __shared__ __align__(16) float pool[Dc];
    pool[t] = g_pooled[b*Dc + t];
    __syncthreads();
    const float4* p4 = (const float4*)pool;
    const float4* w = (const float4*)(ctx_w + (size_t)t*Dc);
    float acc = ctx_b[t];
    #pragma unroll 8
    for (int e = 0; e < Dc/4; e++) {
        float4 wv = w[e], pv = p4[e];
        acc += wv.x*pv.x + wv.y*pv.y + wv.z*pv.z + wv.w*pv.w;
    }
    g_cq[b*Dc + t] = acc;
    if (t < Qc) {
        const float4* gw = (const float4*)(gate_w + (size_t)t*Dc);
        float a2 = gate_b[t];
        #pragma unroll 8
        for (int e = 0; e < Dc/4; e++) {
            float4 wv = gw[e], pv = p4[e];
            a2 += wv.x*pv.x + wv.y*pv.y + wv.z*pv.z + wv.w*pv.w;
        }
        out[OFF_G + b*Qc + t] = 1.0f/(1.0f + expf(-a2));
    }
}
__global__ void k_queries_qs(const float* __restrict__ qp, const float* __restrict__ in_w,
                             const float* __restrict__ in_b, float* __restrict__ out) {
    int bid = blockIdx.x; int b = bid >> 5, q = bid & 31; int t = threadIdx.x;
    __shared__ __align__(16) float qrow[Dc];
    __shared__ __align__(16) float qs_s[Dc];
    for (int i = t; i < Dc; i += 256) {
        float v = qp[q*Dc + i] + g_cq[b*Dc + i];
        qrow[i] = v;
        out[OFF_Q + (size_t)bid*Dc + i] = v;
    }
    __syncthreads();
    const float4* q4 = (const float4*)qrow;
    for (int f = t; f < Dc; f += 256) {
        const float4* w = (const float4*)(in_w + (size_t)f*Dc);
        float acc = in_b[f];
        #pragma unroll 8
        for (int e = 0; e < Dc/4; e++) {
            float4 wv = w[e], pv = q4[e];
            acc += wv.x*pv.x + wv.y*pv.y + wv.z*pv.z + wv.w*pv.w;
        }
        float v = acc * 0.125f;
        qs_s[f] = v;
        g_qs[(size_t)bid*Dc + f] = v;
    }
    __syncthreads();
    if (t < Hc) {
        float s = 0.f;
        #pragma unroll
        for (int hd = 0; hd < HDc; hd++) s += qs_s[t*HDc + hd] * in_b[Dc + t*HDc + hd];
        g_qkb[b*HQc + t*Qc + q] = s;
    }
}
// 8-row blocks (1024 total) for latency hiding; emits fp16 A1
__global__ __launch_bounds__(128) void k_qk(const float* __restrict__ in_w) {
    int h = blockIdx.x, r0 = blockIdx.y*8, t = threadIdx.x;
    int c = blockIdx.z*128 + t;
    __shared__ float A[8][65];
    for (int j = t; j < 8*64; j += 128) A[j>>6][j&63] = g_qs[(size_t)(r0 + (j>>6))*Dc + h*HDc + (j&63)];
    __syncthreads();
    float acc[8];
    #pragma unroll
    for (int r = 0; r < 8; r++) acc[r] = 0.f;
    const float* wk = in_w + (size_t)(Dc + h*HDc)*Dc;
    #pragma unroll 8
    for (int hd = 0; hd < HDc; hd++) {
        float w = wk[(size_t)hd*Dc + c];
        #pragma unroll
        for (int r = 0; r < 8; r++) acc[r] += A[r][hd]*w;
    }
    #pragma unroll
    for (int r = 0; r < 8; r++) {
        int bq = r0 + r; int b = bq >> 5, q = bq & 31;
        g_A1[((size_t)b*HQc + h*Qc + q)*Dc + c] = __float2half_rn(acc[r]);
    }
}

// ---------- gathered conversion: compacted B1 (fp16) + B2 hi/lo (transposed) ----------
__global__ __launch_bounds__(256) void k_convT(const float* __restrict__ mem) {
    int mb = blockIdx.x, db = blockIdx.y, b = blockIdx.z, t = threadIdx.x;
    int m0 = mb*64;
    if (m0 >= g_kpad[b]) return;
    int cnt = g_cnt[b];
    __shared__ int sidx[64];
    __shared__ float s[64][129];
    if (t < 64) { int j = m0 + t; sidx[t] = (j < cnt) ? g_midx[b][j] : 0; }
    __syncthreads();
    int d0 = db*128;
    for (int it = 0; it < 8; it++) {
        int idx = t + it*256; int r = idx >> 5, c4 = idx & 31;
        float4 v = *(const float4*)(mem + ((size_t)b*Mc + sidx[r])*Dc + d0 + c4*4);
        s[r][c4*4+0] = v.x; s[r][c4*4+1] = v.y; s[r][c4*4+2] = v.z; s[r][c4*4+3] = v.w;
    }
    __syncthreads();
    {
        int r = t >> 2, ds = (t & 3)*32;
        size_t base = ((size_t)b*Mc + m0 + r)*Dc + d0 + ds;
        #pragma unroll
        for (int g = 0; g < 4; g++) {
            float v[8];
            #pragma unroll
            for (int j = 0; j < 8; j++) v[j] = s[r][ds + g*8 + j];
            uint4 hv; cvt8h(v, &hv);
            *(uint4*)(g_B1 + base + g*8) = hv;
        }
    }
    for (int it = 0; it < 2; it++) {
        int u = t + it*256; int dl = u >> 2, g = u & 3;
        float v[16];
        #pragma unroll
        for (int j = 0; j < 16; j++) v[j] = s[g*16 + j][dl];
        uint4 h0, l0, h1, l1;
        cvt8hs(v, &h0, &l0); cvt8hs(v + 8, &h1, &l1);
        size_t base = ((size_t)b*Dc + d0 + dl)*Mc + m0 + g*16;
        *(uint4*)(g_B2h + base)     = h0;
        *(uint4*)(g_B2h + base + 8) = h1;
        *(uint4*)(g_B2l + base)     = l0;
        *(uint4*)(g_B2l + base + 8) = l1;
    }
}

// ---------- HMMA GEMM (NT), 128x128 tile, BK=32, fp16 ----------
// MODE 0: scores = A1 @ B1^T, single pass.
// MODE 1: ctx = A2 @ (B2h + B2l)^T, 2 passes, split-K=4.
#define TPAD 80
#define TILE_B 10240
template<int MODE>
__global__ __launch_bounds__(256, 1) void k_gemm() {
    const int T = (MODE == 0) ? 2 : 3;          // tiles per stage
    const int STGSZ = T*TILE_B;
    extern __shared__ __align__(128) unsigned char smraw[];
    uint32_t sb = smem_u32(smraw);
    int tid = threadIdx.x, lane = tid & 31, wid = tid >> 5;
    int wm0 = (wid & 1)*64, wn0 = (wid >> 1)*32;
    int nt = blockIdx.x, mt = blockIdx.y;
    const __half *Ap, *Bph, *Bpl = nullptr;
    int K, NITER, kc0, stride, b, sp = 0;
    if (MODE == 0) {
        b = blockIdx.z; K = Dc; NITER = 16; kc0 = 0; stride = 1;
        if (nt*128 >= g_kpad[b]) return;
        Ap  = g_A1 + (size_t)b*HQc*Dc;
        Bph = g_B1 + (size_t)b*Mc*Dc;
    } else {
        b = blockIdx.z >> 2; sp = blockIdx.z & 3; K = Mc;
        int ch = g_kpad[b] >> 5;
        NITER = (sp < ch) ? ((ch - sp + 3) >> 2) : 0;
        kc0 = sp; stride = 4;
        Ap  = g_A2  + (size_t)b*HQc*Mc;
        Bph = g_B2h + (size_t)b*Dc*Mc;
        Bpl = g_B2l + (size_t)b*Dc*Mc;
    }
    int m0 = mt*128, n0 = nt*128;

    float acc[4][4][4];
    #pragma unroll
    for (int i=0;i<4;i++)
        #pragma unroll
        for (int j=0;j<4;j++)
            #pragma unroll
            for (int e=0;e<4;e++) acc[i][j][e] = 0.f;

    #define LOAD_STAGE(ST, CI) do { \
        int kk_ = (kc0 + (CI)*stride)*32; \
        _Pragma("unroll") \
        for (int i_ = 0; i_ < 2*T; i_++) { \
            int c_ = tid + i_*256; \
            int tau_ = c_ >> 9, rem_ = c_ & 511, row_ = rem_ >> 2, ch_ = rem_ & 3; \
            uint32_t dst_ = sb + (ST)*STGSZ + tau_*TILE_B + row_*TPAD + ch_*16; \
            const __half* src_; \
            if (tau_ == 0)      src_ = Ap  + (size_t)(m0+row_)*K + kk_ + ch_*8; \
            else if (tau_ == 1) src_ = Bph + (size_t)(n0+row_)*K + kk_ + ch_*8; \
            else                src_ = Bpl + (size_t)(n0+row_)*K + kk_ + ch_*8; \
            cp16(dst_, src_); \
        } \
        cp_commit(); \
    } while(0)

    if (NITER > 0) LOAD_STAGE(0, 0); else cp_commit();
    if (NITER > 1) LOAD_STAGE(1, 1); else cp_commit();

    int ra  = wm0 + (lane & 15);
    int ha  = (lane >> 4)*16;
    int rb  = wn0 + ((lane >> 4) << 3) + (lane & 7);
    int hb  = ((lane >> 3) & 1)*16;

    for (int ci = 0; ci < NITER; ci++) {
        cp_wait1();
        __syncthreads();
        int st = ci & 1;
        uint32_t Ats = sb + st*STGSZ;
        uint32_t Bhs = Ats + TILE_B;
        uint32_t Bls = Ats + 2*TILE_B;
        #pragma unroll
        for (int kk = 0; kk < 2; kk++) {
            uint32_t ah[4][4], bb[4][2];
            #pragma unroll
            for (int i = 0; i < 4; i++)
                ldm4(ah[i], Ats + (uint32_t)(ra + i*16)*TPAD + kk*32 + ha);
            #pragma unroll
            for (int j2 = 0; j2 < 2; j2++) {
                uint32_t t4[4];
                ldm4(t4, Bhs + (uint32_t)(rb + j2*16)*TPAD + kk*32 + hb);
                bb[j2*2][0]=t4[0]; bb[j2*2][1]=t4[1]; bb[j2*2+1][0]=t4[2]; bb[j2*2+1][1]=t4[3];
            }
            #pragma unroll
            for (int i=0;i<4;i++)
                #pragma unroll
                for (int j=0;j<4;j++) mma16816(acc[i][j], ah[i], bb[j]);
            if (MODE == 1) {
                #pragma unroll
                for (int j2 = 0; j2 < 2; j2++) {
                    uint32_t t4[4];
                    ldm4(t4, Bls + (uint32_t)(rb + j2*16)*TPAD + kk*32 + hb);
                    bb[j2*2][0]=t4[0]; bb[j2*2][1]=t4[1]; bb[j2*2+1][0]=t4[2]; bb[j2*2+1][1]=t4[3];
                }
                #pragma unroll
                for (int i=0;i<4;i++)
                    #pragma unroll
                    for (int j=0;j<4;j++) mma16816(acc[i][j], ah[i], bb[j]);
            }
        }
        __syncthreads();
        if (ci + 2 < NITER) { LOAD_STAGE(st, ci + 2); } else { cp_commit(); }
    }

    int row4 = lane >> 2, col2 = (lane & 3)*2;
    #pragma unroll
    for (int i = 0; i < 4; i++) {
        #pragma unroll
        for (int rr = 0; rr < 2; rr++) {
            int r = m0 + wm0 + i*16 + row4 + rr*8;
            if (MODE == 0) {
                float kb = g_qkb[b*HQc + r];
                float* dst = g_attn + ((size_t)b*HQc + r)*Mc + n0 + wn0;
                #pragma unroll
                for (int j = 0; j < 4; j++) {
                    float2 v = make_float2(acc[i][j][rr*2] + kb, acc[i][j][rr*2+1] + kb);
                    *(float2*)(dst + j*8 + col2) = v;
                }
            } else {
                float* dst = g_ctxp[sp] + ((size_t)b*HQc + r)*Dc + n0 + wn0;
                #pragma unroll
                for (int j = 0; j < 4; j++) {
                    float2 v = make_float2(acc[i][j][rr*2], acc[i][j][rr*2+1]);
                    *(float2*)(dst + j*8 + col2) = v;
                }
            }
        }
    }
    #undef LOAD_STAGE
}

// ---------- fused softmax (compacted, kpad-bounded) + head-mean scatter + A2 fp16 ----------
__global__ __launch_bounds__(512) void k_softmax_mean(const int* __restrict__ mask,
                                                      float* __restrict__ out) {
    int bid = blockIdx.x; int b = bid >> 5, q = bid & 31; int t = threadIdx.x;
    int lane = t & 31, wid = t >> 5;
    int cnt = g_cnt[b], kpad = g_kpad[b];
    __shared__ float red[16]; __shared__ float bcs[2];
    uint32_t mbits = 0;
    {
        const int4* mk = (const int4*)(mask + (size_t)b*Mc + t*16);
        #pragma unroll
        for (int i = 0; i < 4; i++) {
            int4 mm = mk[i];
            if (mm.x) mbits |= 1u << (i*4+0);
            if (mm.y) mbits |= 1u << (i*4+1);
            if (mm.z) mbits |= 1u << (i*4+2);
            if (mm.w) mbits |= 1u << (i*4+3);
        }
    }
    int j0 = t*16;
    bool active = j0 < kpad;
    float macc[16];
    #pragma unroll
    for (int i = 0; i < 16; i++) macc[i] = 0.f;

    for (int h = 0; h < Hc; h++) {
        size_t row = (size_t)b*HQc + h*Qc + q;
        const float4* rp = (const float4*)(g_attn + row*Mc + j0);
        float v[16];
        if (active) {
            #pragma unroll
            for (int i = 0; i < 4; i++) {
                float4 x = rp[i];
                v[i*4+0] = (j0 + i*4 + 0 < cnt) ? x.x : -INFINITY;
                v[i*4+1] = (j0 + i*4 + 1 < cnt) ? x.y : -INFINITY;
                v[i*4+2] = (j0 + i*4 + 2 < cnt) ? x.z : -INFINITY;
                v[i*4+3] = (j0 + i*4 + 3 < cnt) ? x.w : -INFINITY;
            }
        } else {
            #pragma unroll
            for (int i = 0; i < 16; i++) v[i] = -INFINITY;
        }
        float mx = -INFINITY;
        #pragma unroll
        for (int i = 0; i < 16; i++) mx = fmaxf(mx, v[i]);
        #pragma unroll
        for (int o = 16; o > 0; o >>= 1) mx = fmaxf(mx, __shfl_xor_sync(0xffffffffu, mx, o));
        if (lane == 0) red[wid] = mx;
        __syncthreads();
        if (t < 32) {
            float y = (lane < 16) ? red[lane] : -INFINITY;
            #pragma unroll
            for (int o = 8; o > 0; o >>= 1) y = fmaxf(y, __shfl_xor_sync(0xffffffffu, y, o));
            if (t == 0) bcs[0] = y;
        }
        __syncthreads();
        float rowmax = bcs[0];
        float s = 0.f;
        #pragma unroll
        for (int i = 0; i < 16; i++) { float e = __expf(v[i] - rowmax); v[i] = e; s += e; }
        #pragma unroll
        for (int o = 16; o > 0; o >>= 1) s += __shfl_xor_sync(0xffffffffu, s, o);
        if (lane == 0) red[wid] = s;
        __syncthreads();
        if (t < 32) {
            float y = (lane < 16) ? red[lane] : 0.f;
            #pragma unroll
            for (int o = 8; o > 0; o >>= 1) y += __shfl_xor_sync(0xffffffffu, y, o);
            if (t == 0) bcs[1] = 1.0f / y;
        }
        __syncthreads();
        float inv = bcs[1];
        #pragma unroll
        for (int i = 0; i < 16; i++) {
            v[i] = (j0 + i < cnt) ? v[i]*inv : 0.f;
            macc[i] += v[i];
        }
        if (active) {
            size_t abase = row*Mc + j0;
            uint4 u0, u1;
            cvt8h(v, &u0); cvt8h(v + 8, &u1);
            *(uint4*)(g_A2 + abase)     = u0;
            *(uint4*)(g_A2 + abase + 8) = u1;
        }
        __syncthreads();
    }
    float* orow = out + OFF_A + (size_t)bid*Mc;
    #pragma unroll
    for (int i = 0; i < 16; i++) {
        int o = j0 + i;
        if (!((mbits >> i) & 1)) orow[o] = 0.f;
    }
    #pragma unroll
    for (int i = 0; i < 16; i++) {
        int j = j0 + i;
        if (j < cnt) orow[g_midx[b][j]] = macc[i]*0.125f;
    }
}

// ---------- epilogue (full-batch, 4 split-K partials) ----------
__global__ __launch_bounds__(256) void k_epilogue(const float* __restrict__ in_w,
        const float* __restrict__ in_b, const float* __restrict__ out_w,
        const float* __restrict__ out_b, const float* __restrict__ ln_g,
        const float* __restrict__ ln_b, float* __restrict__ out) {
    int b = blockIdx.x, q = blockIdx.y, t = threadIdx.x;
    __shared__ __align__(16) float cm[Hc][Dc];
    __shared__ __align__(16) float co[Dc];
    __shared__ float rsum[8], rsq[8], bcs[2];
    #pragma unroll
    for (int j = 0; j < 16; j++) {
        int idx = t + j*256; int h = idx >> 9, e = idx & 511;
        size_t off = ((size_t)b*HQc + h*Qc + q)*Dc + e;
        float s = 0.f;
        #pragma unroll
        for (int sp = 0; sp < 4; sp++) s += g_ctxp[sp][off];
        cm[h][e] = s;
    }
    __syncthreads();
    for (int f = t; f < Dc; f += 256) {
        int h = f >> 6;
        const float4* w  = (const float4*)(in_w + (size_t)(2*Dc + f)*Dc);
        const float4* c4 = (const float4*)cm[h];
        float acc = in_b[2*Dc + f];
        #pragma unroll 8
        for (int e = 0; e < Dc/4; e++) {
            float4 wv = w[e], cv = c4[e];
            acc += wv.x*cv.x + wv.y*cv.y + wv.z*cv.z + wv.w*cv.w;
        }
        co[f] = acc;
    }
    __syncthreads();
    float g = out[OFF_G + b*Qc + q];
    const float4* co4 = (const float4*)co;
    float r[2];
    #pragma unroll
    for (int half = 0; half < 2; half++) {
        int d = t + half*256;
        const float4* w = (const float4*)(out_w + (size_t)d*Dc);
        float acc = out_b[d];
        #pragma unroll 8
        for (int e = 0; e < Dc/4; e++) {
            float4 wv = w[e], cv = co4[e];
            acc += wv.x*cv.x + wv.y*cv.y + wv.z*cv.z + wv.w*cv.w;
        }
        r[half] = acc * g;
    }
    float ssum = r[0] + r[1];
    float ssq  = r[0]*r[0] + r[1]*r[1];
    #pragma unroll
    for (int o = 16; o > 0; o >>= 1) {
        ssum += __shfl_xor_sync(0xffffffffu, ssum, o);
        ssq  += __shfl_xor_sync(0xffffffffu, ssq,  o);
    }
    if ((t & 31) == 0) { rsum[t >> 5] = ssum; rsq[t >> 5] = ssq; }
    __syncthreads();
    if (t == 0) {
        float S = 0.f, SQ = 0.f;
        #pragma unroll
        for (int i = 0; i < 8; i++) { S += rsum[i]; SQ += rsq[i]; }
        float mu = S * (1.0f/Dc);
        float var = SQ * (1.0f/Dc) - mu*mu;
        bcs[0] = mu; bcs[1] = rsqrtf(var + 1e-5f);
    }
    __syncthreads();
    float mu = bcs[0], rs = bcs[1];
    size_t obase = OFF_R + ((size_t)(b*Qc + q))*Dc;
    #pragma unroll
    for (int half = 0; half < 2; half++) {
        int d = t + half*256;
        out[obase + d] = (r[half] - mu)*rs*ln_g[d] + ln_b[d];
    }
}

// ---------- launch: single-stream main chain + convT fork ----------
extern "C" void kernel_launch(void* const* d_in, const int* in_sizes, int n_in,
                              void* d_out, int out_size) {
    const float* memory  = (const float*)d_in[0];
    const float* context = (const float*)d_in[1];
    const int*   mask    = (const int*)d_in[2];
    const float* qp      = (const float*)d_in[3];
    const float* ctx_w   = (const float*)d_in[4];
    const float* ctx_b   = (const float*)d_in[5];
    const float* in_w    = (const float*)d_in[6];
    const float* in_b    = (const float*)d_in[7];
    const float* out_w   = (const float*)d_in[8];
    const float* out_b   = (const float*)d_in[9];
    const float* ln_g    = (const float*)d_in[10];
    const float* ln_b    = (const float*)d_in[11];
    const float* gate_w  = (const float*)d_in[12];
    const float* gate_b  = (const float*)d_in[13];
    float* out = (float*)d_out;

    static cudaStream_t s1 = nullptr;
    static cudaEvent_t evA, evC;
    if (!s1) {
        cudaStreamCreateWithFlags(&s1, cudaStreamNonBlocking);
        cudaEventCreateWithFlags(&evA, cudaEventDisableTiming);
        cudaEventCreateWithFlags(&evC, cudaEventDisableTiming);
        cudaFuncSetAttribute(k_gemm<0>, cudaFuncAttributeMaxDynamicSharedMemorySize, 2*2*TILE_B);
        cudaFuncSetAttribute(k_gemm<1>, cudaFuncAttributeMaxDynamicSharedMemorySize, 2*3*TILE_B);
    }

    // fork: mask scan + gathered conversion concurrent with q-chain
    cudaEventRecord(evA, 0);
    cudaStreamWaitEvent(s1, evA, 0);

    k_pooled      <<<Bc, Dc>>>(context);
    k_cq_gates    <<<Bc, Dc>>>(ctx_w, ctx_b, gate_w, gate_b, out);
    k_queries_qs  <<<Bc*Qc, 256>>>(qp, in_w, in_b, out);
    k_qk          <<<dim3(Hc, 32, 4), 128>>>(in_w);

    k_mask_scan   <<<Bc, 1024, 0, s1>>>(mask);
    k_convT       <<<dim3(128, 4, Bc), 256, 0, s1>>>(memory);
    cudaEventRecord(evC, s1);
    cudaStreamWaitEvent(0, evC, 0);

    k_gemm<0>     <<<dim3(64, 2, Bc), 256, 2*2*TILE_B>>>();
    k_softmax_mean<<<Bc*Qc, 512>>>(mask, out);
    k_gemm<1>     <<<dim3(4, 2, Bc*4), 256, 2*3*TILE_B>>>();
    k_epilogue    <<<dim3(Bc, Qc), 256>>>(in_w, in_b, out_w, out_b, ln_g, ln_b, out);
}

// round 15
// speedup vs baseline: 1.7951x; 1.1278x over previous
#include <cuda_runtime.h>
#include <cuda_fp16.h>
#include <math.h>
#include <stdint.h>

#define Bc 8
#define Mc 8192
#define Sc 128
#define Dc 512
#define Qc 32
#define Hc 8
#define HDc 64
#define HQc 256

#define OFF_R 0
#define OFF_A (Bc*Qc*Dc)
#define OFF_G (OFF_A + Bc*Qc*Mc)
#define OFF_Q (OFF_G + Bc*Qc)

__device__ float g_cq[Bc*Dc];
__device__ float g_qs[Bc*Qc*Dc];
__device__ float g_qkb[Bc*HQc];
__device__ __align__(16) __half g_scores[(size_t)Bc*HQc*Mc];  // compacted raw scores (fp16)
__device__ float g_ctxp[4][(size_t)Bc*HQc*Dc];
__device__ int   g_midx[Bc][Mc];
__device__ int   g_cnt[Bc];
__device__ int   g_kpad[Bc];
__device__ __align__(16) __half g_A1[(size_t)Bc*HQc*Dc];      // qk fp16
__device__ __align__(16) __half g_B1[(size_t)Bc*Mc*Dc];       // compacted memory fp16
__device__ __align__(16) __half g_A2[(size_t)Bc*HQc*Mc];      // compacted attn fp16
__device__ __align__(16) __half g_B2[(size_t)Bc*Dc*Mc];       // compacted memory^T fp16

__device__ __forceinline__ void cvt8h(const float* v, uint4* o){
    union { uint4 u; __half h[8]; } a;
    #pragma unroll
    for (int j=0;j<8;j++) a.h[j] = __float2half_rn(v[j]);
    *o = a.u;
}
__device__ __forceinline__ uint32_t smem_u32(const void* p){
    uint32_t a;
    asm("{ .reg .u64 t; cvta.to.shared.u64 t, %1; cvt.u32.u64 %0, t; }" : "=r"(a) : "l"(p));
    return a;
}
__device__ __forceinline__ void cp16(uint32_t dst, const void* src){
    asm volatile("cp.async.cg.shared.global [%0], [%1], 16;" :: "r"(dst), "l"(src));
}
__device__ __forceinline__ void cp_commit(){ asm volatile("cp.async.commit_group;" ::: "memory"); }
__device__ __forceinline__ void cp_wait1(){ asm volatile("cp.async.wait_group 1;" ::: "memory"); }
__device__ __forceinline__ void ldm4(uint32_t* r, uint32_t a){
    asm volatile("ldmatrix.sync.aligned.m8n8.x4.shared.b16 {%0,%1,%2,%3}, [%4];"
      : "=r"(r[0]),"=r"(r[1]),"=r"(r[2]),"=r"(r[3]) : "r"(a));
}
__device__ __forceinline__ void mma16816(float* c, const uint32_t* a, const uint32_t* b){
    asm volatile("mma.sync.aligned.m16n8k16.row.col.f32.f16.f16.f32 "
      "{%0,%1,%2,%3}, {%4,%5,%6,%7}, {%8,%9}, {%0,%1,%2,%3};"
      : "+f"(c[0]),"+f"(c[1]),"+f"(c[2]),"+f"(c[3])
      : "r"(a[0]),"r"(a[1]),"r"(a[2]),"r"(a[3]), "r"(b[0]),"r"(b[1]));
}

// ---------- mask prefix-scan ----------
__global__ __launch_bounds__(1024) void k_mask_scan(const int* __restrict__ mask){
    int b = blockIdx.x, t = threadIdx.x;
    __shared__ int wsum[32];
    for (int j = t; j < Mc; j += 1024) g_midx[b][j] = 0;
    __syncthreads();
    int bits[8]; int loc = 0;
    #pragma unroll
    for (int i = 0; i < 8; i++) { bits[i] = (mask[(size_t)b*Mc + t*8 + i] != 0); loc += bits[i]; }
    int lane = t & 31, w = t >> 5;
    int x = loc;
    #pragma unroll
    for (int o = 1; o < 32; o <<= 1) { int y = __shfl_up_sync(0xffffffffu, x, o); if (lane >= o) x += y; }
    if (lane == 31) wsum[w] = x;
    __syncthreads();
    if (t < 32) {
        int y = wsum[t];
        #pragma unroll
        for (int o = 1; o < 32; o <<= 1) { int z = __shfl_up_sync(0xffffffffu, y, o); if (t >= o) y += z; }
        wsum[t] = y;
    }
    __syncthreads();
    int base = x - loc + (w ? wsum[w-1] : 0);
    #pragma unroll
    for (int i = 0; i < 8; i++) if (bits[i]) g_midx[b][base++] = t*8 + i;
    if (t == 0) { int cnt = wsum[31]; g_cnt[b] = cnt; g_kpad[b] = ((cnt + 127) >> 7) << 7; }
}

// ---------- fused pooled + cq + gates ----------
__global__ __launch_bounds__(512) void k_pool_cq(const float* __restrict__ ctx,
        const float* __restrict__ ctx_w, const float* __restrict__ ctx_b,
        const float* __restrict__ gate_w, const float* __restrict__ gate_b,
        float* __restrict__ out) {
    int b = blockIdx.x, t = threadIdx.x;
    __shared__ __align__(16) float pool[Dc];
    if (t < Dc) {
        const float* p = ctx + (size_t)b*Sc*Dc + t;
        float s = 0.f;
        #pragma unroll 8
        for (int i = 0; i < Sc; i++) s += p[(size_t)i*Dc];
        pool[t] = s * (1.0f/Sc);
    }
    __syncthreads();
    const float4* p4 = (const float4*)pool;
    if (t < Dc) {
        const float4* w = (const float4*)(ctx_w + (size_t)t*Dc);
        float acc = ctx_b[t];
        #pragma unroll 8
        for (int e = 0; e < Dc/4; e++) {
            float4 wv = w[e], pv = p4[e];
            acc += wv.x*pv.x + wv.y*pv.y + wv.z*pv.z + wv.w*pv.w;
        }
        g_cq[b*Dc + t] = acc;
    }
    if (t < Qc) {
        const float4* gw = (const float4*)(gate_w + (size_t)t*Dc);
        float a2 = gate_b[t];
        #pragma unroll 8
        for (int e = 0; e < Dc/4; e++) {
            float4 wv = gw[e], pv = p4[e];
            a2 += wv.x*pv.x + wv.y*pv.y + wv.z*pv.z + wv.w*pv.w;
        }
        out[OFF_G + b*Qc + t] = 1.0f/(1.0f + expf(-a2));
    }
}
__global__ void k_queries_qs(const float* __restrict__ qp, const float* __restrict__ in_w,
                             const float* __restrict__ in_b, float* __restrict__ out) {
    int bid = blockIdx.x; int b = bid >> 5, q = bid & 31; int t = threadIdx.x;
    __shared__ __align__(16) float qrow[Dc];
    __shared__ __align__(16) float qs_s[Dc];
    for (int i = t; i < Dc; i += 256) {
        float v = qp[q*Dc + i] + g_cq[b*Dc + i];
        qrow[i] = v;
        out[OFF_Q + (size_t)bid*Dc + i] = v;
    }
    __syncthreads();
    const float4* q4 = (const float4*)qrow;
    for (int f = t; f < Dc; f += 256) {
        const float4* w = (const float4*)(in_w + (size_t)f*Dc);
        float acc = in_b[f];
        #pragma unroll 8
        for (int e = 0; e < Dc/4; e++) {
            float4 wv = w[e], pv = q4[e];
            acc += wv.x*pv.x + wv.y*pv.y + wv.z*pv.z + wv.w*pv.w;
        }
        float v = acc * 0.125f;
        qs_s[f] = v;
        g_qs[(size_t)bid*Dc + f] = v;
    }
    __syncthreads();
    if (t < Hc) {
        float s = 0.f;
        #pragma unroll
        for (int hd = 0; hd < HDc; hd++) s += qs_s[t*HDc + hd] * in_b[Dc + t*HDc + hd];
        g_qkb[b*HQc + t*Qc + q] = s;
    }
}
// 2 columns per thread for load ILP; emits fp16 A1
__global__ __launch_bounds__(128) void k_qk(const float* __restrict__ in_w) {
    int h = blockIdx.x, r0 = blockIdx.y*8, t = threadIdx.x;
    int c = blockIdx.z*256 + t;
    __shared__ float A[8][65];
    for (int j = t; j < 8*64; j += 128) A[j>>6][j&63] = g_qs[(size_t)(r0 + (j>>6))*Dc + h*HDc + (j&63)];
    __syncthreads();
    float acc0[8], acc1[8];
    #pragma unroll
    for (int r = 0; r < 8; r++) { acc0[r] = 0.f; acc1[r] = 0.f; }
    const float* wk = in_w + (size_t)(Dc + h*HDc)*Dc;
    #pragma unroll 8
    for (int hd = 0; hd < HDc; hd++) {
        float w0 = wk[(size_t)hd*Dc + c];
        float w1 = wk[(size_t)hd*Dc + c + 128];
        #pragma unroll
        for (int r = 0; r < 8; r++) { float a = A[r][hd]; acc0[r] += a*w0; acc1[r] += a*w1; }
    }
    #pragma unroll
    for (int r = 0; r < 8; r++) {
        int bq = r0 + r; int b = bq >> 5, q = bq & 31;
        size_t idx = ((size_t)b*HQc + h*Qc + q)*Dc;
        g_A1[idx + c]       = __float2half_rn(acc0[r]);
        g_A1[idx + c + 128] = __float2half_rn(acc1[r]);
    }
}

// ---------- gathered conversion: compacted B1 (fp16) + B2 (transposed fp16) ----------
__global__ __launch_bounds__(256) void k_convT(const float* __restrict__ mem) {
    int mb = blockIdx.x, db = blockIdx.y, b = blockIdx.z, t = threadIdx.x;
    int m0 = mb*64;
    if (m0 >= g_kpad[b]) return;
    int cnt = g_cnt[b];
    __shared__ int sidx[64];
    __shared__ float s[64][129];
    if (t < 64) { int j = m0 + t; sidx[t] = (j < cnt) ? g_midx[b][j] : 0; }
    __syncthreads();
    int d0 = db*128;
    for (int it = 0; it < 8; it++) {
        int idx = t + it*256; int r = idx >> 5, c4 = idx & 31;
        float4 v = *(const float4*)(mem + ((size_t)b*Mc + sidx[r])*Dc + d0 + c4*4);
        s[r][c4*4+0] = v.x; s[r][c4*4+1] = v.y; s[r][c4*4+2] = v.z; s[r][c4*4+3] = v.w;
    }
    __syncthreads();
    {
        int r = t >> 2, ds = (t & 3)*32;
        size_t base = ((size_t)b*Mc + m0 + r)*Dc + d0 + ds;
        #pragma unroll
        for (int g = 0; g < 4; g++) {
            float v[8];
            #pragma unroll
            for (int j = 0; j < 8; j++) v[j] = s[r][ds + g*8 + j];
            uint4 hv; cvt8h(v, &hv);
            *(uint4*)(g_B1 + base + g*8) = hv;
        }
    }
    for (int it = 0; it < 2; it++) {
        int u = t + it*256; int dl = u >> 2, g = u & 3;
        float v[16];
        #pragma unroll
        for (int j = 0; j < 16; j++) v[j] = s[g*16 + j][dl];
        uint4 h0, h1;
        cvt8h(v, &h0); cvt8h(v + 8, &h1);
        size_t base = ((size_t)b*Dc + d0 + dl)*Mc + m0 + g*16;
        *(uint4*)(g_B2 + base)     = h0;
        *(uint4*)(g_B2 + base + 8) = h1;
    }
}

// ---------- HMMA GEMM (NT), 128x128 tile, BK=32, fp16 single-pass ----------
// MODE 0: scores = A1 @ B1^T -> g_scores (fp16, +bias)
// MODE 1: ctx = A2 @ B2^T -> g_ctxp[sp] (fp32), split-K=4
#define TPAD 80
#define TILE_B 10240
#define STGSZ (2*TILE_B)
#define GSM (2*STGSZ)
template<int MODE>
__global__ __launch_bounds__(256, 1) void k_gemm() {
    extern __shared__ __align__(128) unsigned char smraw[];
    uint32_t sb = smem_u32(smraw);
    int tid = threadIdx.x, lane = tid & 31, wid = tid >> 5;
    int wm0 = (wid & 1)*64, wn0 = (wid >> 1)*32;
    int nt = blockIdx.x, mt = blockIdx.y;
    const __half *Ap, *Bp;
    int K, NITER, kc0, stride, b, sp = 0;
    if (MODE == 0) {
        b = blockIdx.z; K = Dc; NITER = 16; kc0 = 0; stride = 1;
        if (nt*128 >= g_kpad[b]) return;
        Ap = g_A1 + (size_t)b*HQc*Dc;
        Bp = g_B1 + (size_t)b*Mc*Dc;
    } else {
        b = blockIdx.z >> 2; sp = blockIdx.z & 3; K = Mc;
        int ch = g_kpad[b] >> 5;
        NITER = (sp < ch) ? ((ch - sp + 3) >> 2) : 0;
        kc0 = sp; stride = 4;
        Ap = g_A2 + (size_t)b*HQc*Mc;
        Bp = g_B2 + (size_t)b*Dc*Mc;
    }
    int m0 = mt*128, n0 = nt*128;

    float acc[4][4][4];
    #pragma unroll
    for (int i=0;i<4;i++)
        #pragma unroll
        for (int j=0;j<4;j++)
            #pragma unroll
            for (int e=0;e<4;e++) acc[i][j][e] = 0.f;

    #define LOAD_STAGE(ST, CI) do { \
        int kk_ = (kc0 + (CI)*stride)*32; \
        _Pragma("unroll") \
        for (int i_ = 0; i_ < 4; i_++) { \
            int c_ = tid + i_*256; \
            int tau_ = c_ >> 9, rem_ = c_ & 511, row_ = rem_ >> 2, ch_ = rem_ & 3; \
            uint32_t dst_ = sb + (ST)*STGSZ + tau_*TILE_B + row_*TPAD + ch_*16; \
            const __half* src_ = (tau_ == 0) ? Ap + (size_t)(m0+row_)*K + kk_ + ch_*8 \
                                             : Bp + (size_t)(n0+row_)*K + kk_ + ch_*8; \
            cp16(dst_, src_); \
        } \
        cp_commit(); \
    } while(0)

    if (NITER > 0) LOAD_STAGE(0, 0); else cp_commit();
    if (NITER > 1) LOAD_STAGE(1, 1); else cp_commit();

    int ra  = wm0 + (lane & 15);
    int ha  = (lane >> 4)*16;
    int rb  = wn0 + ((lane >> 4) << 3) + (lane & 7);
    int hb  = ((lane >> 3) & 1)*16;

    for (int ci = 0; ci < NITER; ci++) {
        cp_wait1();
        __syncthreads();
        int st = ci & 1;
        uint32_t Ats = sb + st*STGSZ;
        uint32_t Bts = Ats + TILE_B;
        #pragma unroll
        for (int kk = 0; kk < 2; kk++) {
            uint32_t ah[4][4], bb[4][2];
            #pragma unroll
            for (int i = 0; i < 4; i++)
                ldm4(ah[i], Ats + (uint32_t)(ra + i*16)*TPAD + kk*32 + ha);
            #pragma unroll
            for (int j2 = 0; j2 < 2; j2++) {
                uint32_t t4[4];
                ldm4(t4, Bts + (uint32_t)(rb + j2*16)*TPAD + kk*32 + hb);
                bb[j2*2][0]=t4[0]; bb[j2*2][1]=t4[1]; bb[j2*2+1][0]=t4[2]; bb[j2*2+1][1]=t4[3];
            }
            #pragma unroll
            for (int i=0;i<4;i++)
                #pragma unroll
                for (int j=0;j<4;j++) mma16816(acc[i][j], ah[i], bb[j]);
        }
        __syncthreads();
        if (ci + 2 < NITER) { LOAD_STAGE(st, ci + 2); } else { cp_commit(); }
    }

    int row4 = lane >> 2, col2 = (lane & 3)*2;
    #pragma unroll
    for (int i = 0; i < 4; i++) {
        #pragma unroll
        for (int rr = 0; rr < 2; rr++) {
            int r = m0 + wm0 + i*16 + row4 + rr*8;
            if (MODE == 0) {
                float kb = g_qkb[b*HQc + r];
                __half* dst = g_scores + ((size_t)b*HQc + r)*Mc + n0 + wn0;
                #pragma unroll
                for (int j = 0; j < 4; j++) {
                    __half2 v = __floats2half2_rn(acc[i][j][rr*2] + kb, acc[i][j][rr*2+1] + kb);
                    *(__half2*)(dst + j*8 + col2) = v;
                }
            } else {
                float* dst = g_ctxp[sp] + ((size_t)b*HQc + r)*Dc + n0 + wn0;
                #pragma unroll
                for (int j = 0; j < 4; j++) {
                    float2 v = make_float2(acc[i][j][rr*2], acc[i][j][rr*2+1]);
                    *(float2*)(dst + j*8 + col2) = v;
                }
            }
        }
    }
    #undef LOAD_STAGE
}

// ---------- fused softmax (compacted fp16 scores) + head-mean scatter + A2 fp16 ----------
__global__ __launch_bounds__(512) void k_softmax_mean(const int* __restrict__ mask,
                                                      float* __restrict__ out) {
    int bid = blockIdx.x; int b = bid >> 5, q = bid & 31; int t = threadIdx.x;
    int lane = t & 31, wid = t >> 5;
    int cnt = g_cnt[b], kpad = g_kpad[b];
    __shared__ float red[16]; __shared__ float bcs[2];
    uint32_t mbits = 0;
    {
        const int4* mk = (const int4*)(mask + (size_t)b*Mc + t*16);
        #pragma unroll
        for (int i = 0; i < 4; i++) {
            int4 mm = mk[i];
            if (mm.x) mbits |= 1u << (i*4+0);
            if (mm.y) mbits |= 1u << (i*4+1);
            if (mm.z) mbits |= 1u << (i*4+2);
            if (mm.w) mbits |= 1u << (i*4+3);
        }
    }
    int j0 = t*16;
    bool active = j0 < kpad;
    float macc[16];
    #pragma unroll
    for (int i = 0; i < 16; i++) macc[i] = 0.f;

    for (int h = 0; h < Hc; h++) {
        size_t row = (size_t)b*HQc + h*Qc + q;
        float v[16];
        if (active) {
            union { uint4 u[2]; __half hh[16]; } sbuf;
            sbuf.u[0] = *(const uint4*)(g_scores + row*Mc + j0);
            sbuf.u[1] = *(const uint4*)(g_scores + row*Mc + j0 + 8);
            #pragma unroll
            for (int i = 0; i < 16; i++)
                v[i] = (j0 + i < cnt) ? __half2float(sbuf.hh[i]) : -INFINITY;
        } else {
            #pragma unroll
            for (int i = 0; i < 16; i++) v[i] = -INFINITY;
        }
        float mx = -INFINITY;
        #pragma unroll
        for (int i = 0; i < 16; i++) mx = fmaxf(mx, v[i]);
        #pragma unroll
        for (int o = 16; o > 0; o >>= 1) mx = fmaxf(mx, __shfl_xor_sync(0xffffffffu, mx, o));
        if (lane == 0) red[wid] = mx;
        __syncthreads();
        if (t < 32) {
            float y = (lane < 16) ? red[lane] : -INFINITY;
            #pragma unroll
            for (int o = 8; o > 0; o >>= 1) y = fmaxf(y, __shfl_xor_sync(0xffffffffu, y, o));
            if (t == 0) bcs[0] = y;
        }
        __syncthreads();
        float rowmax = bcs[0];
        float s = 0.f;
        #pragma unroll
        for (int i = 0; i < 16; i++) { float e = __expf(v[i] - rowmax); v[i] = e; s += e; }
        #pragma unroll
        for (int o = 16; o > 0; o >>= 1) s += __shfl_xor_sync(0xffffffffu, s, o);
        if (lane == 0) red[wid] = s;
        __syncthreads();
        if (t < 32) {
            float y = (lane < 16) ? red[lane] : 0.f;
            #pragma unroll
            for (int o = 8; o > 0; o >>= 1) y += __shfl_xor_sync(0xffffffffu, y, o);
            if (t == 0) bcs[1] = 1.0f / y;
        }
        __syncthreads();
        float inv = bcs[1];
        #pragma unroll
        for (int i = 0; i < 16; i++) {
            v[i] = (j0 + i < cnt) ? v[i]*inv : 0.f;
            macc[i] += v[i];
        }
        if (active) {
            size_t abase = row*Mc + j0;
            uint4 u0, u1;
            cvt8h(v, &u0); cvt8h(v + 8, &u1);
            *(uint4*)(g_A2 + abase)     = u0;
            *(uint4*)(g_A2 + abase + 8) = u1;
        }
        __syncthreads();
    }
    float* orow = out + OFF_A + (size_t)bid*Mc;
    #pragma unroll
    for (int i = 0; i < 16; i++) {
        int o = j0 + i;
        if (!((mbits >> i) & 1)) orow[o] = 0.f;
    }
    #pragma unroll
    for (int i = 0; i < 16; i++) {
        int j = j0 + i;
        if (j < cnt) orow[g_midx[b][j]] = macc[i]*0.125f;
    }
}

// ---------- epilogue (full-batch, 4 split-K partials) ----------
__global__ __launch_bounds__(256) void k_epilogue(const float* __restrict__ in_w,
        const float* __restrict__ in_b, const float* __restrict__ out_w,
        const float* __restrict__ out_b, const float* __restrict__ ln_g,
        const float* __restrict__ ln_b, float* __restrict__ out) {
    int b = blockIdx.x, q = blockIdx.y, t = threadIdx.x;
    __shared__ __align__(16) float cm[Hc][Dc];
    __shared__ __align__(16) float co[Dc];
    __shared__ float rsum[8], rsq[8], bcs[2];
    #pragma unroll
    for (int j = 0; j < 16; j++) {
        int idx = t + j*256; int h = idx >> 9, e = idx & 511;
        size_t off = ((size_t)b*HQc + h*Qc + q)*Dc + e;
        float s = 0.f;
        #pragma unroll
        for (int sp = 0; sp < 4; sp++) s += g_ctxp[sp][off];
        cm[h][e] = s;
    }
    __syncthreads();
    for (int f = t; f < Dc; f += 256) {
        int h = f >> 6;
        const float4* w  = (const float4*)(in_w + (size_t)(2*Dc + f)*Dc);
        const float4* c4 = (const float4*)cm[h];
        float acc = in_b[2*Dc + f];
        #pragma unroll 8
        for (int e = 0; e < Dc/4; e++) {
            float4 wv = w[e], cv = c4[e];
            acc += wv.x*cv.x + wv.y*cv.y + wv.z*cv.z + wv.w*cv.w;
        }
        co[f] = acc;
    }
    __syncthreads();
    float g = out[OFF_G + b*Qc + q];
    const float4* co4 = (const float4*)co;
    float r[2];
    #pragma unroll
    for (int half = 0; half < 2; half++) {
        int d = t + half*256;
        const float4* w = (const float4*)(out_w + (size_t)d*Dc);
        float acc = out_b[d];
        #pragma unroll 8
        for (int e = 0; e < Dc/4; e++) {
            float4 wv = w[e], cv = co4[e];
            acc += wv.x*cv.x + wv.y*cv.y + wv.z*cv.z + wv.w*cv.w;
        }
        r[half] = acc * g;
    }
    float ssum = r[0] + r[1];
    float ssq  = r[0]*r[0] + r[1]*r[1];
    #pragma unroll
    for (int o = 16; o > 0; o >>= 1) {
        ssum += __shfl_xor_sync(0xffffffffu, ssum, o);
        ssq  += __shfl_xor_sync(0xffffffffu, ssq,  o);
    }
    if ((t & 31) == 0) { rsum[t >> 5] = ssum; rsq[t >> 5] = ssq; }
    __syncthreads();
    if (t == 0) {
        float S = 0.f, SQ = 0.f;
        #pragma unroll
        for (int i = 0; i < 8; i++) { S += rsum[i]; SQ += rsq[i]; }
        float mu = S * (1.0f/Dc);
        float var = SQ * (1.0f/Dc) - mu*mu;
        bcs[0] = mu; bcs[1] = rsqrtf(var + 1e-5f);
    }
    __syncthreads();
    float mu = bcs[0], rs = bcs[1];
    size_t obase = OFF_R + ((size_t)(b*Qc + q))*Dc;
    #pragma unroll
    for (int half = 0; half < 2; half++) {
        int d = t + half*256;
        out[obase + d] = (r[half] - mu)*rs*ln_g[d] + ln_b[d];
    }
}

// ---------- launch: single-stream main chain + convT fork ----------
extern "C" void kernel_launch(void* const* d_in, const int* in_sizes, int n_in,
                              void* d_out, int out_size) {
    const float* memory  = (const float*)d_in[0];
    const float* context = (const float*)d_in[1];
    const int*   mask    = (const int*)d_in[2];
    const float* qp      = (const float*)d_in[3];
    const float* ctx_w   = (const float*)d_in[4];
    const float* ctx_b   = (const float*)d_in[5];
    const float* in_w    = (const float*)d_in[6];
    const float* in_b    = (const float*)d_in[7];
    const float* out_w   = (const float*)d_in[8];
    const float* out_b   = (const float*)d_in[9];
    const float* ln_g    = (const float*)d_in[10];
    const float* ln_b    = (const float*)d_in[11];
    const float* gate_w  = (const float*)d_in[12];
    const float* gate_b  = (const float*)d_in[13];
    float* out = (float*)d_out;

    static cudaStream_t s1 = nullptr;
    static cudaEvent_t evA, evC;
    if (!s1) {
        cudaStreamCreateWithFlags(&s1, cudaStreamNonBlocking);
        cudaEventCreateWithFlags(&evA, cudaEventDisableTiming);
        cudaEventCreateWithFlags(&evC, cudaEventDisableTiming);
        cudaFuncSetAttribute(k_gemm<0>, cudaFuncAttributeMaxDynamicSharedMemorySize, GSM);
        cudaFuncSetAttribute(k_gemm<1>, cudaFuncAttributeMaxDynamicSharedMemorySize, GSM);
    }

    // fork: mask scan + gathered conversion concurrent with q-chain
    cudaEventRecord(evA, 0);
    cudaStreamWaitEvent(s1, evA, 0);

    k_pool_cq     <<<Bc, 512>>>(context, ctx_w, ctx_b, gate_w, gate_b, out);
    k_queries_qs  <<<Bc*Qc, 256>>>(qp, in_w, in_b, out);
    k_qk          <<<dim3(Hc, 32, 2), 128>>>(in_w);

    k_mask_scan   <<<Bc, 1024, 0, s1>>>(mask);
    k_convT       <<<dim3(128, 4, Bc), 256, 0, s1>>>(memory);
    cudaEventRecord(evC, s1);
    cudaStreamWaitEvent(0, evC, 0);

    k_gemm<0>     <<<dim3(64, 2, Bc), 256, GSM>>>();
    k_softmax_mean<<<Bc*Qc, 512>>>(mask, out);
    k_gemm<1>     <<<dim3(4, 2, Bc*4), 256, GSM>>>();
    k_epilogue    <<<dim3(Bc, Qc), 256>>>(in_w, in_b, out_w, out_b, ln_g, ln_b, out);
}

// round 16
// speedup vs baseline: 2.1005x; 1.1702x over previous
#include <cuda_runtime.h>
#include <cuda_fp16.h>
#include <math.h>
#include <stdint.h>

#define Bc 8
#define Mc 8192
#define Sc 128
#define Dc 512
#define Qc 32
#define Hc 8
#define HDc 64
#define HQc 256

#define OFF_R 0
#define OFF_A (Bc*Qc*Dc)
#define OFF_G (OFF_A + Bc*Qc*Mc)
#define OFF_Q (OFF_G + Bc*Qc)

__device__ float g_cq[Bc*Dc];
__device__ float g_qs[Bc*Qc*Dc];
__device__ float g_qkb[Bc*HQc];
__device__ __align__(16) __half g_scores[(size_t)Bc*HQc*Mc];  // compacted raw scores (fp16)
__device__ float g_ctxp[4][(size_t)Bc*HQc*Dc];
__device__ int   g_midx[Bc][Mc];
__device__ int   g_cnt[Bc];
__device__ int   g_kpad[Bc];
__device__ __align__(16) __half g_A1[(size_t)Bc*HQc*Dc];      // qk fp16
__device__ __align__(16) __half g_B1[(size_t)Bc*Mc*Dc];       // compacted memory fp16
__device__ __align__(16) __half g_A2[(size_t)Bc*HQc*Mc];      // compacted attn fp16
__device__ __align__(16) __half g_B2[(size_t)Bc*Dc*Mc];       // compacted memory^T fp16

__device__ __forceinline__ void cvt8h(const float* v, uint4* o){
    union { uint4 u; __half h[8]; } a;
    #pragma unroll
    for (int j=0;j<8;j++) a.h[j] = __float2half_rn(v[j]);
    *o = a.u;
}
__device__ __forceinline__ uint32_t smem_u32(const void* p){
    uint32_t a;
    asm("{ .reg .u64 t; cvta.to.shared.u64 t, %1; cvt.u32.u64 %0, t; }" : "=r"(a) : "l"(p));
    return a;
}
__device__ __forceinline__ void cp16(uint32_t dst, const void* src){
    asm volatile("cp.async.cg.shared.global [%0], [%1], 16;" :: "r"(dst), "l"(src));
}
__device__ __forceinline__ void cp_commit(){ asm volatile("cp.async.commit_group;" ::: "memory"); }
__device__ __forceinline__ void cp_wait1(){ asm volatile("cp.async.wait_group 1;" ::: "memory"); }
__device__ __forceinline__ void ldm4(uint32_t* r, uint32_t a){
    asm volatile("ldmatrix.sync.aligned.m8n8.x4.shared.b16 {%0,%1,%2,%3}, [%4];"
      : "=r"(r[0]),"=r"(r[1]),"=r"(r[2]),"=r"(r[3]) : "r"(a));
}
__device__ __forceinline__ void mma16816(float* c, const uint32_t* a, const uint32_t* b){
    asm volatile("mma.sync.aligned.m16n8k16.row.col.f32.f16.f16.f32 "
      "{%0,%1,%2,%3}, {%4,%5,%6,%7}, {%8,%9}, {%0,%1,%2,%3};"
      : "+f"(c[0]),"+f"(c[1]),"+f"(c[2]),"+f"(c[3])
      : "r"(a[0]),"r"(a[1]),"r"(a[2]),"r"(a[3]), "r"(b[0]),"r"(b[1]));
}

// ---------- mask prefix-scan ----------
__global__ __launch_bounds__(1024) void k_mask_scan(const int* __restrict__ mask){
    int b = blockIdx.x, t = threadIdx.x;
    __shared__ int wsum[32];
    for (int j = t; j < Mc; j += 1024) g_midx[b][j] = 0;
    __syncthreads();
    int bits[8]; int loc = 0;
    #pragma unroll
    for (int i = 0; i < 8; i++) { bits[i] = (mask[(size_t)b*Mc + t*8 + i] != 0); loc += bits[i]; }
    int lane = t & 31, w = t >> 5;
    int x = loc;
    #pragma unroll
    for (int o = 1; o < 32; o <<= 1) { int y = __shfl_up_sync(0xffffffffu, x, o); if (lane >= o) x += y; }
    if (lane == 31) wsum[w] = x;
    __syncthreads();
    if (t < 32) {
        int y = wsum[t];
        #pragma unroll
        for (int o = 1; o < 32; o <<= 1) { int z = __shfl_up_sync(0xffffffffu, y, o); if (t >= o) y += z; }
        wsum[t] = y;
    }
    __syncthreads();
    int base = x - loc + (w ? wsum[w-1] : 0);
    #pragma unroll
    for (int i = 0; i < 8; i++) if (bits[i]) g_midx[b][base++] = t*8 + i;
    if (t == 0) { int cnt = wsum[31]; g_cnt[b] = cnt; g_kpad[b] = ((cnt + 127) >> 7) << 7; }
}

// ---------- fused pooled + cq + gates ----------
__global__ __launch_bounds__(512) void k_pool_cq(const float* __restrict__ ctx,
        const float* __restrict__ ctx_w, const float* __restrict__ ctx_b,
        const float* __restrict__ gate_w, const float* __restrict__ gate_b,
        float* __restrict__ out) {
    int b = blockIdx.x, t = threadIdx.x;
    __shared__ __align__(16) float pool[Dc];
    if (t < Dc) {
        const float* p = ctx + (size_t)b*Sc*Dc + t;
        float s = 0.f;
        #pragma unroll 8
        for (int i = 0; i < Sc; i++) s += p[(size_t)i*Dc];
        pool[t] = s * (1.0f/Sc);
    }
    __syncthreads();
    const float4* p4 = (const float4*)pool;
    if (t < Dc) {
        const float4* w = (const float4*)(ctx_w + (size_t)t*Dc);
        float acc = ctx_b[t];
        #pragma unroll 8
        for (int e = 0; e < Dc/4; e++) {
            float4 wv = w[e], pv = p4[e];
            acc += wv.x*pv.x + wv.y*pv.y + wv.z*pv.z + wv.w*pv.w;
        }
        g_cq[b*Dc + t] = acc;
    }
    if (t < Qc) {
        const float4* gw = (const float4*)(gate_w + (size_t)t*Dc);
        float a2 = gate_b[t];
        #pragma unroll 8
        for (int e = 0; e < Dc/4; e++) {
            float4 wv = gw[e], pv = p4[e];
            a2 += wv.x*pv.x + wv.y*pv.y + wv.z*pv.z + wv.w*pv.w;
        }
        out[OFF_G + b*Qc + t] = 1.0f/(1.0f + expf(-a2));
    }
}
__global__ void k_queries_qs(const float* __restrict__ qp, const float* __restrict__ in_w,
                             const float* __restrict__ in_b, float* __restrict__ out) {
    int bid = blockIdx.x; int b = bid >> 5, q = bid & 31; int t = threadIdx.x;
    __shared__ __align__(16) float qrow[Dc];
    __shared__ __align__(16) float qs_s[Dc];
    for (int i = t; i < Dc; i += 256) {
        float v = qp[q*Dc + i] + g_cq[b*Dc + i];
        qrow[i] = v;
        out[OFF_Q + (size_t)bid*Dc + i] = v;
    }
    __syncthreads();
    const float4* q4 = (const float4*)qrow;
    for (int f = t; f < Dc; f += 256) {
        const float4* w = (const float4*)(in_w + (size_t)f*Dc);
        float acc = in_b[f];
        #pragma unroll 8
        for (int e = 0; e < Dc/4; e++) {
            float4 wv = w[e], pv = q4[e];
            acc += wv.x*pv.x + wv.y*pv.y + wv.z*pv.z + wv.w*pv.w;
        }
        float v = acc * 0.125f;
        qs_s[f] = v;
        g_qs[(size_t)bid*Dc + f] = v;
    }
    __syncthreads();
    if (t < Hc) {
        float s = 0.f;
        #pragma unroll
        for (int hd = 0; hd < HDc; hd++) s += qs_s[t*HDc + hd] * in_b[Dc + t*HDc + hd];
        g_qkb[b*HQc + t*Qc + q] = s;
    }
}
// 2 columns per thread for load ILP; emits fp16 A1
__global__ __launch_bounds__(128) void k_qk(const float* __restrict__ in_w) {
    int h = blockIdx.x, r0 = blockIdx.y*8, t = threadIdx.x;
    int c = blockIdx.z*256 + t;
    __shared__ float A[8][65];
    for (int j = t; j < 8*64; j += 128) A[j>>6][j&63] = g_qs[(size_t)(r0 + (j>>6))*Dc + h*HDc + (j&63)];
    __syncthreads();
    float acc0[8], acc1[8];
    #pragma unroll
    for (int r = 0; r < 8; r++) { acc0[r] = 0.f; acc1[r] = 0.f; }
    const float* wk = in_w + (size_t)(Dc + h*HDc)*Dc;
    #pragma unroll 8
    for (int hd = 0; hd < HDc; hd++) {
        float w0 = wk[(size_t)hd*Dc + c];
        float w1 = wk[(size_t)hd*Dc + c + 128];
        #pragma unroll
        for (int r = 0; r < 8; r++) { float a = A[r][hd]; acc0[r] += a*w0; acc1[r] += a*w1; }
    }
    #pragma unroll
    for (int r = 0; r < 8; r++) {
        int bq = r0 + r; int b = bq >> 5, q = bq & 31;
        size_t idx = ((size_t)b*HQc + h*Qc + q)*Dc;
        g_A1[idx + c]       = __float2half_rn(acc0[r]);
        g_A1[idx + c + 128] = __float2half_rn(acc1[r]);
    }
}

// ---------- gathered conversion: compacted B1 (fp16) + B2 (transposed fp16) ----------
__global__ __launch_bounds__(256) void k_convT(const float* __restrict__ mem) {
    int mb = blockIdx.x, db = blockIdx.y, b = blockIdx.z, t = threadIdx.x;
    int m0 = mb*64;
    if (m0 >= g_kpad[b]) return;
    int cnt = g_cnt[b];
    __shared__ int sidx[64];
    __shared__ float s[64][129];
    if (t < 64) { int j = m0 + t; sidx[t] = (j < cnt) ? g_midx[b][j] : 0; }
    __syncthreads();
    int d0 = db*128;
    for (int it = 0; it < 8; it++) {
        int idx = t + it*256; int r = idx >> 5, c4 = idx & 31;
        float4 v = *(const float4*)(mem + ((size_t)b*Mc + sidx[r])*Dc + d0 + c4*4);
        s[r][c4*4+0] = v.x; s[r][c4*4+1] = v.y; s[r][c4*4+2] = v.z; s[r][c4*4+3] = v.w;
    }
    __syncthreads();
    {
        int r = t >> 2, ds = (t & 3)*32;
        size_t base = ((size_t)b*Mc + m0 + r)*Dc + d0 + ds;
        #pragma unroll
        for (int g = 0; g < 4; g++) {
            float v[8];
            #pragma unroll
            for (int j = 0; j < 8; j++) v[j] = s[r][ds + g*8 + j];
            uint4 hv; cvt8h(v, &hv);
            *(uint4*)(g_B1 + base + g*8) = hv;
        }
    }
    for (int it = 0; it < 2; it++) {
        int u = t + it*256; int dl = u >> 2, g = u & 3;
        float v[16];
        #pragma unroll
        for (int j = 0; j < 16; j++) v[j] = s[g*16 + j][dl];
        uint4 h0, h1;
        cvt8h(v, &h0); cvt8h(v + 8, &h1);
        size_t base = ((size_t)b*Dc + d0 + dl)*Mc + m0 + g*16;
        *(uint4*)(g_B2 + base)     = h0;
        *(uint4*)(g_B2 + base + 8) = h1;
    }
}

// ---------- HMMA GEMM (NT), 128x128 tile, BK=32, fp16 single-pass ----------
#define TPAD 80
#define TILE_B 10240
#define STGSZ (2*TILE_B)
#define GSM (2*STGSZ)
template<int MODE>
__global__ __launch_bounds__(256, 1) void k_gemm() {
    extern __shared__ __align__(128) unsigned char smraw[];
    uint32_t sb = smem_u32(smraw);
    int tid = threadIdx.x, lane = tid & 31, wid = tid >> 5;
    int wm0 = (wid & 1)*64, wn0 = (wid >> 1)*32;
    int nt = blockIdx.x, mt = blockIdx.y;
    const __half *Ap, *Bp;
    int K, NITER, kc0, stride, b, sp = 0;
    if (MODE == 0) {
        b = blockIdx.z; K = Dc; NITER = 16; kc0 = 0; stride = 1;
        if (nt*128 >= g_kpad[b]) return;
        Ap = g_A1 + (size_t)b*HQc*Dc;
        Bp = g_B1 + (size_t)b*Mc*Dc;
    } else {
        b = blockIdx.z >> 2; sp = blockIdx.z & 3; K = Mc;
        int ch = g_kpad[b] >> 5;
        NITER = (sp < ch) ? ((ch - sp + 3) >> 2) : 0;
        kc0 = sp; stride = 4;
        Ap = g_A2 + (size_t)b*HQc*Mc;
        Bp = g_B2 + (size_t)b*Dc*Mc;
    }
    int m0 = mt*128, n0 = nt*128;

    float acc[4][4][4];
    #pragma unroll
    for (int i=0;i<4;i++)
        #pragma unroll
        for (int j=0;j<4;j++)
            #pragma unroll
            for (int e=0;e<4;e++) acc[i][j][e] = 0.f;

    #define LOAD_STAGE(ST, CI) do { \
        int kk_ = (kc0 + (CI)*stride)*32; \
        _Pragma("unroll") \
        for (int i_ = 0; i_ < 4; i_++) { \
            int c_ = tid + i_*256; \
            int tau_ = c_ >> 9, rem_ = c_ & 511, row_ = rem_ >> 2, ch_ = rem_ & 3; \
            uint32_t dst_ = sb + (ST)*STGSZ + tau_*TILE_B + row_*TPAD + ch_*16; \
            const __half* src_ = (tau_ == 0) ? Ap + (size_t)(m0+row_)*K + kk_ + ch_*8 \
                                             : Bp + (size_t)(n0+row_)*K + kk_ + ch_*8; \
            cp16(dst_, src_); \
        } \
        cp_commit(); \
    } while(0)

    if (NITER > 0) LOAD_STAGE(0, 0); else cp_commit();
    if (NITER > 1) LOAD_STAGE(1, 1); else cp_commit();

    int ra  = wm0 + (lane & 15);
    int ha  = (lane >> 4)*16;
    int rb  = wn0 + ((lane >> 4) << 3) + (lane & 7);
    int hb  = ((lane >> 3) & 1)*16;

    for (int ci = 0; ci < NITER; ci++) {
        cp_wait1();
        __syncthreads();
        int st = ci & 1;
        uint32_t Ats = sb + st*STGSZ;
        uint32_t Bts = Ats + TILE_B;
        #pragma unroll
        for (int kk = 0; kk < 2; kk++) {
            uint32_t ah[4][4], bb[4][2];
            #pragma unroll
            for (int i = 0; i < 4; i++)
                ldm4(ah[i], Ats + (uint32_t)(ra + i*16)*TPAD + kk*32 + ha);
            #pragma unroll
            for (int j2 = 0; j2 < 2; j2++) {
                uint32_t t4[4];
                ldm4(t4, Bts + (uint32_t)(rb + j2*16)*TPAD + kk*32 + hb);
                bb[j2*2][0]=t4[0]; bb[j2*2][1]=t4[1]; bb[j2*2+1][0]=t4[2]; bb[j2*2+1][1]=t4[3];
            }
            #pragma unroll
            for (int i=0;i<4;i++)
                #pragma unroll
                for (int j=0;j<4;j++) mma16816(acc[i][j], ah[i], bb[j]);
        }
        __syncthreads();
        if (ci + 2 < NITER) { LOAD_STAGE(st, ci + 2); } else { cp_commit(); }
    }

    int row4 = lane >> 2, col2 = (lane & 3)*2;
    #pragma unroll
    for (int i = 0; i < 4; i++) {
        #pragma unroll
        for (int rr = 0; rr < 2; rr++) {
            int r = m0 + wm0 + i*16 + row4 + rr*8;
            if (MODE == 0) {
                float kb = g_qkb[b*HQc + r];
                __half* dst = g_scores + ((size_t)b*HQc + r)*Mc + n0 + wn0;
                #pragma unroll
                for (int j = 0; j < 4; j++) {
                    __half2 v = __floats2half2_rn(acc[i][j][rr*2] + kb, acc[i][j][rr*2+1] + kb);
                    *(__half2*)(dst + j*8 + col2) = v;
                }
            } else {
                float* dst = g_ctxp[sp] + ((size_t)b*HQc + r)*Dc + n0 + wn0;
                #pragma unroll
                for (int j = 0; j < 4; j++) {
                    float2 v = make_float2(acc[i][j][rr*2], acc[i][j][rr*2+1]);
                    *(float2*)(dst + j*8 + col2) = v;
                }
            }
        }
    }
    #undef LOAD_STAGE
}

// ---------- fused softmax (no-max, compacted fp16 scores) + head-mean scatter + A2 ----------
__global__ __launch_bounds__(512) void k_softmax_mean(const int* __restrict__ mask,
                                                      float* __restrict__ out) {
    int bid = blockIdx.x; int b = bid >> 5, q = bid & 31; int t = threadIdx.x;
    int lane = t & 31, wid = t >> 5;
    int cnt = g_cnt[b], kpad = g_kpad[b];
    __shared__ float red[16]; __shared__ float bcs;
    uint32_t mbits = 0;
    {
        const int4* mk = (const int4*)(mask + (size_t)b*Mc + t*16);
        #pragma unroll
        for (int i = 0; i < 4; i++) {
            int4 mm = mk[i];
            if (mm.x) mbits |= 1u << (i*4+0);
            if (mm.y) mbits |= 1u << (i*4+1);
            if (mm.z) mbits |= 1u << (i*4+2);
            if (mm.w) mbits |= 1u << (i*4+3);
        }
    }
    int j0 = t*16;
    bool active = j0 < kpad;
    float macc[16];
    #pragma unroll
    for (int i = 0; i < 16; i++) macc[i] = 0.f;

    for (int h = 0; h < Hc; h++) {
        size_t row = (size_t)b*HQc + h*Qc + q;
        float v[16];
        float s = 0.f;
        if (active) {
            union { uint4 u[2]; __half hh[16]; } sbuf;
            sbuf.u[0] = *(const uint4*)(g_scores + row*Mc + j0);
            sbuf.u[1] = *(const uint4*)(g_scores + row*Mc + j0 + 8);
            #pragma unroll
            for (int i = 0; i < 16; i++) {
                float e = (j0 + i < cnt) ? __expf(__half2float(sbuf.hh[i])) : 0.f;
                v[i] = e; s += e;
            }
        } else {
            #pragma unroll
            for (int i = 0; i < 16; i++) v[i] = 0.f;
        }
        #pragma unroll
        for (int o = 16; o > 0; o >>= 1) s += __shfl_xor_sync(0xffffffffu, s, o);
        if (lane == 0) red[wid] = s;
        __syncthreads();
        if (t < 32) {
            float y = (lane < 16) ? red[lane] : 0.f;
            #pragma unroll
            for (int o = 8; o > 0; o >>= 1) y += __shfl_xor_sync(0xffffffffu, y, o);
            if (t == 0) bcs = 1.0f / y;
        }
        __syncthreads();
        float inv = bcs;
        #pragma unroll
        for (int i = 0; i < 16; i++) {
            v[i] *= inv;
            macc[i] += v[i];
        }
        if (active) {
            size_t abase = row*Mc + j0;
            uint4 u0, u1;
            cvt8h(v, &u0); cvt8h(v + 8, &u1);
            *(uint4*)(g_A2 + abase)     = u0;
            *(uint4*)(g_A2 + abase + 8) = u1;
        }
        __syncthreads();
    }
    float* orow = out + OFF_A + (size_t)bid*Mc;
    #pragma unroll
    for (int i = 0; i < 16; i++) {
        int o = j0 + i;
        if (!((mbits >> i) & 1)) orow[o] = 0.f;
    }
    #pragma unroll
    for (int i = 0; i < 16; i++) {
        int j = j0 + i;
        if (j < cnt) orow[g_midx[b][j]] = macc[i]*0.125f;
    }
}

// ---------- epilogue: 2 q per block (weight-row reuse), 4 split-K partials ----------
__global__ __launch_bounds__(256) void k_epilogue(const float* __restrict__ in_w,
        const float* __restrict__ in_b, const float* __restrict__ out_w,
        const float* __restrict__ out_b, const float* __restrict__ ln_g,
        const float* __restrict__ ln_b, float* __restrict__ out) {
    int b = blockIdx.x, q0 = blockIdx.y*2, t = threadIdx.x;
    __shared__ __align__(16) float cm[2][Hc][Dc];   // 32 KB
    __shared__ __align__(16) float co[2][Dc];       // 4 KB
    __shared__ float rsum[2][8], rsq[2][8], bcs[2][2];
    #pragma unroll
    for (int j = 0; j < 32; j++) {
        int idx = t + j*256; int qq = idx >> 12; int h = (idx >> 9) & 7; int e = idx & 511;
        size_t off = ((size_t)b*HQc + h*Qc + q0 + qq)*Dc + e;
        float s = 0.f;
        #pragma unroll
        for (int sp = 0; sp < 4; sp++) s += g_ctxp[sp][off];
        cm[qq][h][e] = s;
    }
    __syncthreads();
    for (int f = t; f < Dc; f += 256) {
        int h = f >> 6;
        const float4* w  = (const float4*)(in_w + (size_t)(2*Dc + f)*Dc);
        const float4* c0 = (const float4*)cm[0][h];
        const float4* c1 = (const float4*)cm[1][h];
        float bias = in_b[2*Dc + f];
        float a0 = bias, a1 = bias;
        #pragma unroll 8
        for (int e = 0; e < Dc/4; e++) {
            float4 wv = w[e];
            float4 v0 = c0[e], v1 = c1[e];
            a0 += wv.x*v0.x + wv.y*v0.y + wv.z*v0.z + wv.w*v0.w;
            a1 += wv.x*v1.x + wv.y*v1.y + wv.z*v1.z + wv.w*v1.w;
        }
        co[0][f] = a0; co[1][f] = a1;
    }
    __syncthreads();
    float g0 = out[OFF_G + b*Qc + q0];
    float g1 = out[OFF_G + b*Qc + q0 + 1];
    const float4* co0 = (const float4*)co[0];
    const float4* co1 = (const float4*)co[1];
    float r[2][2];
    #pragma unroll
    for (int half = 0; half < 2; half++) {
        int d = t + half*256;
        const float4* w = (const float4*)(out_w + (size_t)d*Dc);
        float bias = out_b[d];
        float a0 = bias, a1 = bias;
        #pragma unroll 8
        for (int e = 0; e < Dc/4; e++) {
            float4 wv = w[e];
            float4 v0 = co0[e], v1 = co1[e];
            a0 += wv.x*v0.x + wv.y*v0.y + wv.z*v0.z + wv.w*v0.w;
            a1 += wv.x*v1.x + wv.y*v1.y + wv.z*v1.z + wv.w*v1.w;
        }
        r[0][half] = a0 * g0;
        r[1][half] = a1 * g1;
    }
    float s0 = r[0][0] + r[0][1], sq0 = r[0][0]*r[0][0] + r[0][1]*r[0][1];
    float s1 = r[1][0] + r[1][1], sq1 = r[1][0]*r[1][0] + r[1][1]*r[1][1];
    #pragma unroll
    for (int o = 16; o > 0; o >>= 1) {
        s0  += __shfl_xor_sync(0xffffffffu, s0,  o);
        sq0 += __shfl_xor_sync(0xffffffffu, sq0, o);
        s1  += __shfl_xor_sync(0xffffffffu, s1,  o);
        sq1 += __shfl_xor_sync(0xffffffffu, sq1, o);
    }
    if ((t & 31) == 0) {
        rsum[0][t >> 5] = s0; rsq[0][t >> 5] = sq0;
        rsum[1][t >> 5] = s1; rsq[1][t >> 5] = sq1;
    }
    __syncthreads();
    if (t < 2) {
        float S = 0.f, SQ = 0.f;
        #pragma unroll
        for (int i = 0; i < 8; i++) { S += rsum[t][i]; SQ += rsq[t][i]; }
        float mu = S * (1.0f/Dc);
        float var = SQ * (1.0f/Dc) - mu*mu;
        bcs[t][0] = mu; bcs[t][1] = rsqrtf(var + 1e-5f);
    }
    __syncthreads();
    #pragma unroll
    for (int qq = 0; qq < 2; qq++) {
        float mu = bcs[qq][0], rs = bcs[qq][1];
        size_t obase = OFF_R + ((size_t)(b*Qc + q0 + qq))*Dc;
        #pragma unroll
        for (int half = 0; half < 2; half++) {
            int d = t + half*256;
            out[obase + d] = (r[qq][half] - mu)*rs*ln_g[d] + ln_b[d];
        }
    }
}

// ---------- launch: single-stream main chain + convT fork ----------
extern "C" void kernel_launch(void* const* d_in, const int* in_sizes, int n_in,
                              void* d_out, int out_size) {
    const float* memory  = (const float*)d_in[0];
    const float* context = (const float*)d_in[1];
    const int*   mask    = (const int*)d_in[2];
    const float* qp      = (const float*)d_in[3];
    const float* ctx_w   = (const float*)d_in[4];
    const float* ctx_b   = (const float*)d_in[5];
    const float* in_w    = (const float*)d_in[6];
    const float* in_b    = (const float*)d_in[7];
    const float* out_w   = (const float*)d_in[8];
    const float* out_b   = (const float*)d_in[9];
    const float* ln_g    = (const float*)d_in[10];
    const float* ln_b    = (const float*)d_in[11];
    const float* gate_w  = (const float*)d_in[12];
    const float* gate_b  = (const float*)d_in[13];
    float* out = (float*)d_out;

    static cudaStream_t s1 = nullptr;
    static cudaEvent_t evA, evC;
    if (!s1) {
        cudaStreamCreateWithFlags(&s1, cudaStreamNonBlocking);
        cudaEventCreateWithFlags(&evA, cudaEventDisableTiming);
        cudaEventCreateWithFlags(&evC, cudaEventDisableTiming);
        cudaFuncSetAttribute(k_gemm<0>, cudaFuncAttributeMaxDynamicSharedMemorySize, GSM);
        cudaFuncSetAttribute(k_gemm<1>, cudaFuncAttributeMaxDynamicSharedMemorySize, GSM);
    }

    // fork: mask scan + gathered conversion concurrent with q-chain
    cudaEventRecord(evA, 0);
    cudaStreamWaitEvent(s1, evA, 0);

    k_pool_cq     <<<Bc, 512>>>(context, ctx_w, ctx_b, gate_w, gate_b, out);
    k_queries_qs  <<<Bc*Qc, 256>>>(qp, in_w, in_b, out);
    k_qk          <<<dim3(Hc, 32, 2), 128>>>(in_w);

    k_mask_scan   <<<Bc, 1024, 0, s1>>>(mask);
    k_convT       <<<dim3(128, 4, Bc), 256, 0, s1>>>(memory);
    cudaEventRecord(evC, s1);
    cudaStreamWaitEvent(0, evC, 0);

    k_gemm<0>     <<<dim3(64, 2, Bc), 256, GSM>>>();
    k_softmax_mean<<<Bc*Qc, 512>>>(mask, out);
    k_gemm<1>     <<<dim3(4, 2, Bc*4), 256, GSM>>>();
    k_epilogue    <<<dim3(Bc, 16), 256>>>(in_w, in_b, out_w, out_b, ln_g, ln_b, out);
}

// round 17
// speedup vs baseline: 2.1287x; 1.0134x over previous
#include <cuda_runtime.h>
#include <cuda_fp16.h>
#include <math.h>
#include <stdint.h>

#define Bc 8
#define Mc 8192
#define Sc 128
#define Dc 512
#define Qc 32
#define Hc 8
#define HDc 64
#define HQc 256

#define OFF_R 0
#define OFF_A (Bc*Qc*Dc)
#define OFF_G (OFF_A + Bc*Qc*Mc)
#define OFF_Q (OFF_G + Bc*Qc)

__device__ float g_cq[Bc*Dc];
__device__ float g_qs[Bc*Qc*Dc];
__device__ float g_qkb[Bc*HQc];
__device__ float g_rsinv[Bc*HQc];                             // 1/rowsum of exp
__device__ __align__(16) __half g_scores[(size_t)Bc*HQc*Mc];  // exp(score) fp16, compacted
__device__ float g_ctxp[4][(size_t)Bc*HQc*Dc];
__device__ int   g_midx[Bc][Mc];
__device__ int   g_cnt[Bc];
__device__ int   g_kpad[Bc];
__device__ __align__(16) __half g_A1[(size_t)Bc*HQc*Dc];      // qk fp16
__device__ __align__(16) __half g_B1[(size_t)Bc*Mc*Dc];       // compacted memory fp16 (pad rows zero)
__device__ __align__(16) __half g_B2[(size_t)Bc*Dc*Mc];       // compacted memory^T fp16 (pad cols zero)

__device__ __forceinline__ void cvt8h(const float* v, uint4* o){
    union { uint4 u; __half h[8]; } a;
    #pragma unroll
    for (int j=0;j<8;j++) a.h[j] = __float2half_rn(v[j]);
    *o = a.u;
}
__device__ __forceinline__ uint32_t smem_u32(const void* p){
    uint32_t a;
    asm("{ .reg .u64 t; cvta.to.shared.u64 t, %1; cvt.u32.u64 %0, t; }" : "=r"(a) : "l"(p));
    return a;
}
__device__ __forceinline__ void cp16(uint32_t dst, const void* src){
    asm volatile("cp.async.cg.shared.global [%0], [%1], 16;" :: "r"(dst), "l"(src));
}
__device__ __forceinline__ void cp_commit(){ asm volatile("cp.async.commit_group;" ::: "memory"); }
__device__ __forceinline__ void cp_wait1(){ asm volatile("cp.async.wait_group 1;" ::: "memory"); }
__device__ __forceinline__ void ldm4(uint32_t* r, uint32_t a){
    asm volatile("ldmatrix.sync.aligned.m8n8.x4.shared.b16 {%0,%1,%2,%3}, [%4];"
      : "=r"(r[0]),"=r"(r[1]),"=r"(r[2]),"=r"(r[3]) : "r"(a));
}
__device__ __forceinline__ void mma16816(float* c, const uint32_t* a, const uint32_t* b){
    asm volatile("mma.sync.aligned.m16n8k16.row.col.f32.f16.f16.f32 "
      "{%0,%1,%2,%3}, {%4,%5,%6,%7}, {%8,%9}, {%0,%1,%2,%3};"
      : "+f"(c[0]),"+f"(c[1]),"+f"(c[2]),"+f"(c[3])
      : "r"(a[0]),"r"(a[1]),"r"(a[2]),"r"(a[3]), "r"(b[0]),"r"(b[1]));
}

// ---------- mask prefix-scan ----------
__global__ __launch_bounds__(1024) void k_mask_scan(const int* __restrict__ mask){
    int b = blockIdx.x, t = threadIdx.x;
    __shared__ int wsum[32];
    for (int j = t; j < Mc; j += 1024) g_midx[b][j] = 0;
    __syncthreads();
    int bits[8]; int loc = 0;
    #pragma unroll
    for (int i = 0; i < 8; i++) { bits[i] = (mask[(size_t)b*Mc + t*8 + i] != 0); loc += bits[i]; }
    int lane = t & 31, w = t >> 5;
    int x = loc;
    #pragma unroll
    for (int o = 1; o < 32; o <<= 1) { int y = __shfl_up_sync(0xffffffffu, x, o); if (lane >= o) x += y; }
    if (lane == 31) wsum[w] = x;
    __syncthreads();
    if (t < 32) {
        int y = wsum[t];
        #pragma unroll
        for (int o = 1; o < 32; o <<= 1) { int z = __shfl_up_sync(0xffffffffu, y, o); if (t >= o) y += z; }
        wsum[t] = y;
    }
    __syncthreads();
    int base = x - loc + (w ? wsum[w-1] : 0);
    #pragma unroll
    for (int i = 0; i < 8; i++) if (bits[i]) g_midx[b][base++] = t*8 + i;
    if (t == 0) { int cnt = wsum[31]; g_cnt[b] = cnt; g_kpad[b] = ((cnt + 127) >> 7) << 7; }
}

// ---------- fused pooled + cq + gates ----------
__global__ __launch_bounds__(512) void k_pool_cq(const float* __restrict__ ctx,
        const float* __restrict__ ctx_w, const float* __restrict__ ctx_b,
        const float* __restrict__ gate_w, const float* __restrict__ gate_b,
        float* __restrict__ out) {
    int b = blockIdx.x, t = threadIdx.x;
    __shared__ __align__(16) float pool[Dc];
    if (t < Dc) {
        const float* p = ctx + (size_t)b*Sc*Dc + t;
        float s = 0.f;
        #pragma unroll 8
        for (int i = 0; i < Sc; i++) s += p[(size_t)i*Dc];
        pool[t] = s * (1.0f/Sc);
    }
    __syncthreads();
    const float4* p4 = (const float4*)pool;
    if (t < Dc) {
        const float4* w = (const float4*)(ctx_w + (size_t)t*Dc);
        float acc = ctx_b[t];
        #pragma unroll 8
        for (int e = 0; e < Dc/4; e++) {
            float4 wv = w[e], pv = p4[e];
            acc += wv.x*pv.x + wv.y*pv.y + wv.z*pv.z + wv.w*pv.w;
        }
        g_cq[b*Dc + t] = acc;
    }
    if (t < Qc) {
        const float4* gw = (const float4*)(gate_w + (size_t)t*Dc);
        float a2 = gate_b[t];
        #pragma unroll 8
        for (int e = 0; e < Dc/4; e++) {
            float4 wv = gw[e], pv = p4[e];
            a2 += wv.x*pv.x + wv.y*pv.y + wv.z*pv.z + wv.w*pv.w;
        }
        out[OFF_G + b*Qc + t] = 1.0f/(1.0f + expf(-a2));
    }
}
__global__ void k_queries_qs(const float* __restrict__ qp, const float* __restrict__ in_w,
                             const float* __restrict__ in_b, float* __restrict__ out) {
    int bid = blockIdx.x; int b = bid >> 5, q = bid & 31; int t = threadIdx.x;
    __shared__ __align__(16) float qrow[Dc];
    __shared__ __align__(16) float qs_s[Dc];
    for (int i = t; i < Dc; i += 256) {
        float v = qp[q*Dc + i] + g_cq[b*Dc + i];
        qrow[i] = v;
        out[OFF_Q + (size_t)bid*Dc + i] = v;
    }
    __syncthreads();
    const float4* q4 = (const float4*)qrow;
    for (int f = t; f < Dc; f += 256) {
        const float4* w = (const float4*)(in_w + (size_t)f*Dc);
        float acc = in_b[f];
        #pragma unroll 8
        for (int e = 0; e < Dc/4; e++) {
            float4 wv = w[e], pv = q4[e];
            acc += wv.x*pv.x + wv.y*pv.y + wv.z*pv.z + wv.w*pv.w;
        }
        float v = acc * 0.125f;
        qs_s[f] = v;
        g_qs[(size_t)bid*Dc + f] = v;
    }
    __syncthreads();
    if (t < Hc) {
        float s = 0.f;
        #pragma unroll
        for (int hd = 0; hd < HDc; hd++) s += qs_s[t*HDc + hd] * in_b[Dc + t*HDc + hd];
        g_qkb[b*HQc + t*Qc + q] = s;
    }
}
// 2 columns per thread for load ILP; emits fp16 A1
__global__ __launch_bounds__(128) void k_qk(const float* __restrict__ in_w) {
    int h = blockIdx.x, r0 = blockIdx.y*8, t = threadIdx.x;
    int c = blockIdx.z*256 + t;
    __shared__ float A[8][65];
    for (int j = t; j < 8*64; j += 128) A[j>>6][j&63] = g_qs[(size_t)(r0 + (j>>6))*Dc + h*HDc + (j&63)];
    __syncthreads();
    float acc0[8], acc1[8];
    #pragma unroll
    for (int r = 0; r < 8; r++) { acc0[r] = 0.f; acc1[r] = 0.f; }
    const float* wk = in_w + (size_t)(Dc + h*HDc)*Dc;
    #pragma unroll 8
    for (int hd = 0; hd < HDc; hd++) {
        float w0 = wk[(size_t)hd*Dc + c];
        float w1 = wk[(size_t)hd*Dc + c + 128];
        #pragma unroll
        for (int r = 0; r < 8; r++) { float a = A[r][hd]; acc0[r] += a*w0; acc1[r] += a*w1; }
    }
    #pragma unroll
    for (int r = 0; r < 8; r++) {
        int bq = r0 + r; int b = bq >> 5, q = bq & 31;
        size_t idx = ((size_t)b*HQc + h*Qc + q)*Dc;
        g_A1[idx + c]       = __float2half_rn(acc0[r]);
        g_A1[idx + c + 128] = __float2half_rn(acc1[r]);
    }
}

// ---------- gathered conversion: compacted B1 + B2 fp16, pad rows/cols ZERO ----------
__global__ __launch_bounds__(256) void k_convT(const float* __restrict__ mem) {
    int mb = blockIdx.x, db = blockIdx.y, b = blockIdx.z, t = threadIdx.x;
    int m0 = mb*64;
    if (m0 >= g_kpad[b]) return;
    int cnt = g_cnt[b];
    __shared__ int sidx[64];
    __shared__ float s[64][129];
    if (t < 64) { int j = m0 + t; sidx[t] = (j < cnt) ? g_midx[b][j] : -1; }
    __syncthreads();
    int d0 = db*128;
    for (int it = 0; it < 8; it++) {
        int idx = t + it*256; int r = idx >> 5, c4 = idx & 31;
        int src = sidx[r];
        float4 v = (src >= 0) ? *(const float4*)(mem + ((size_t)b*Mc + src)*Dc + d0 + c4*4)
                              : make_float4(0.f, 0.f, 0.f, 0.f);
        s[r][c4*4+0] = v.x; s[r][c4*4+1] = v.y; s[r][c4*4+2] = v.z; s[r][c4*4+3] = v.w;
    }
    __syncthreads();
    {
        int r = t >> 2, ds = (t & 3)*32;
        size_t base = ((size_t)b*Mc + m0 + r)*Dc + d0 + ds;
        #pragma unroll
        for (int g = 0; g < 4; g++) {
            float v[8];
            #pragma unroll
            for (int j = 0; j < 8; j++) v[j] = s[r][ds + g*8 + j];
            uint4 hv; cvt8h(v, &hv);
            *(uint4*)(g_B1 + base + g*8) = hv;
        }
    }
    for (int it = 0; it < 2; it++) {
        int u = t + it*256; int dl = u >> 2, g = u & 3;
        float v[16];
        #pragma unroll
        for (int j = 0; j < 16; j++) v[j] = s[g*16 + j][dl];
        uint4 h0, h1;
        cvt8h(v, &h0); cvt8h(v + 8, &h1);
        size_t base = ((size_t)b*Dc + d0 + dl)*Mc + m0 + g*16;
        *(uint4*)(g_B2 + base)     = h0;
        *(uint4*)(g_B2 + base + 8) = h1;
    }
}

// ---------- HMMA GEMM (NT), 128x128 tile, BK=32, fp16 single-pass ----------
// MODE 0: p = exp(A1 @ B1^T + bias) -> g_scores (fp16)
// MODE 1: ctx_unnorm = exp_scores @ B2^T -> g_ctxp[sp] (fp32), split-K=4
#define TPAD 80
#define TILE_B 10240
#define STGSZ (2*TILE_B)
#define GSM (2*STGSZ)
template<int MODE>
__global__ __launch_bounds__(256, 1) void k_gemm() {
    extern __shared__ __align__(128) unsigned char smraw[];
    uint32_t sb = smem_u32(smraw);
    int tid = threadIdx.x, lane = tid & 31, wid = tid >> 5;
    int wm0 = (wid & 1)*64, wn0 = (wid >> 1)*32;
    int nt = blockIdx.x, mt = blockIdx.y;
    const __half *Ap, *Bp;
    int K, NITER, kc0, stride, b, sp = 0;
    if (MODE == 0) {
        b = blockIdx.z; K = Dc; NITER = 16; kc0 = 0; stride = 1;
        if (nt*128 >= g_kpad[b]) return;
        Ap = g_A1 + (size_t)b*HQc*Dc;
        Bp = g_B1 + (size_t)b*Mc*Dc;
    } else {
        b = blockIdx.z >> 2; sp = blockIdx.z & 3; K = Mc;
        int ch = g_kpad[b] >> 5;
        NITER = (sp < ch) ? ((ch - sp + 3) >> 2) : 0;
        kc0 = sp; stride = 4;
        Ap = g_scores + (size_t)b*HQc*Mc;
        Bp = g_B2 + (size_t)b*Dc*Mc;
    }
    int m0 = mt*128, n0 = nt*128;

    float acc[4][4][4];
    #pragma unroll
    for (int i=0;i<4;i++)
        #pragma unroll
        for (int j=0;j<4;j++)
            #pragma unroll
            for (int e=0;e<4;e++) acc[i][j][e] = 0.f;

    #define LOAD_STAGE(ST, CI) do { \
        int kk_ = (kc0 + (CI)*stride)*32; \
        _Pragma("unroll") \
        for (int i_ = 0; i_ < 4; i_++) { \
            int c_ = tid + i_*256; \
            int tau_ = c_ >> 9, rem_ = c_ & 511, row_ = rem_ >> 2, ch_ = rem_ & 3; \
            uint32_t dst_ = sb + (ST)*STGSZ + tau_*TILE_B + row_*TPAD + ch_*16; \
            const __half* src_ = (tau_ == 0) ? Ap + (size_t)(m0+row_)*K + kk_ + ch_*8 \
                                             : Bp + (size_t)(n0+row_)*K + kk_ + ch_*8; \
            cp16(dst_, src_); \
        } \
        cp_commit(); \
    } while(0)

    if (NITER > 0) LOAD_STAGE(0, 0); else cp_commit();
    if (NITER > 1) LOAD_STAGE(1, 1); else cp_commit();

    int ra  = wm0 + (lane & 15);
    int ha  = (lane >> 4)*16;
    int rb  = wn0 + ((lane >> 4) << 3) + (lane & 7);
    int hb  = ((lane >> 3) & 1)*16;

    for (int ci = 0; ci < NITER; ci++) {
        cp_wait1();
        __syncthreads();
        int st = ci & 1;
        uint32_t Ats = sb + st*STGSZ;
        uint32_t Bts = Ats + TILE_B;
        #pragma unroll
        for (int kk = 0; kk < 2; kk++) {
            uint32_t ah[4][4], bb[4][2];
            #pragma unroll
            for (int i = 0; i < 4; i++)
                ldm4(ah[i], Ats + (uint32_t)(ra + i*16)*TPAD + kk*32 + ha);
            #pragma unroll
            for (int j2 = 0; j2 < 2; j2++) {
                uint32_t t4[4];
                ldm4(t4, Bts + (uint32_t)(rb + j2*16)*TPAD + kk*32 + hb);
                bb[j2*2][0]=t4[0]; bb[j2*2][1]=t4[1]; bb[j2*2+1][0]=t4[2]; bb[j2*2+1][1]=t4[3];
            }
            #pragma unroll
            for (int i=0;i<4;i++)
                #pragma unroll
                for (int j=0;j<4;j++) mma16816(acc[i][j], ah[i], bb[j]);
        }
        __syncthreads();
        if (ci + 2 < NITER) { LOAD_STAGE(st, ci + 2); } else { cp_commit(); }
    }

    int row4 = lane >> 2, col2 = (lane & 3)*2;
    #pragma unroll
    for (int i = 0; i < 4; i++) {
        #pragma unroll
        for (int rr = 0; rr < 2; rr++) {
            int r = m0 + wm0 + i*16 + row4 + rr*8;
            if (MODE == 0) {
                float kb = g_qkb[b*HQc + r];
                __half* dst = g_scores + ((size_t)b*HQc + r)*Mc + n0 + wn0;
                #pragma unroll
                for (int j = 0; j < 4; j++) {
                    float p0 = __expf(acc[i][j][rr*2]   + kb);
                    float p1 = __expf(acc[i][j][rr*2+1] + kb);
                    *(__half2*)(dst + j*8 + col2) = __floats2half2_rn(p0, p1);
                }
            } else {
                float* dst = g_ctxp[sp] + ((size_t)b*HQc + r)*Dc + n0 + wn0;
                #pragma unroll
                for (int j = 0; j < 4; j++) {
                    float2 v = make_float2(acc[i][j][rr*2], acc[i][j][rr*2+1]);
                    *(float2*)(dst + j*8 + col2) = v;
                }
            }
        }
    }
    #undef LOAD_STAGE
}

// ---------- fused row-sum + head-mean scatter (no exp, no A2 write) ----------
__global__ __launch_bounds__(512) void k_softmax_mean(const int* __restrict__ mask,
                                                      float* __restrict__ out) {
    int bid = blockIdx.x; int b = bid >> 5, q = bid & 31; int t = threadIdx.x;
    int lane = t & 31, wid = t >> 5;
    int cnt = g_cnt[b], kpad = g_kpad[b];
    __shared__ float red[16]; __shared__ float bcs;
    uint32_t mbits = 0;
    {
        const int4* mk = (const int4*)(mask + (size_t)b*Mc + t*16);
        #pragma unroll
        for (int i = 0; i < 4; i++) {
            int4 mm = mk[i];
            if (mm.x) mbits |= 1u << (i*4+0);
            if (mm.y) mbits |= 1u << (i*4+1);
            if (mm.z) mbits |= 1u << (i*4+2);
            if (mm.w) mbits |= 1u << (i*4+3);
        }
    }
    int j0 = t*16;
    bool active = j0 < kpad;
    float macc[16];
    #pragma unroll
    for (int i = 0; i < 16; i++) macc[i] = 0.f;

    for (int h = 0; h < Hc; h++) {
        size_t row = (size_t)b*HQc + h*Qc + q;
        float v[16];
        float s = 0.f;
        if (active) {
            union { uint4 u[2]; __half hh[16]; } sbuf;
            sbuf.u[0] = *(const uint4*)(g_scores + row*Mc + j0);
            sbuf.u[1] = *(const uint4*)(g_scores + row*Mc + j0 + 8);
            #pragma unroll
            for (int i = 0; i < 16; i++) {
                float e = (j0 + i < cnt) ? __half2float(sbuf.hh[i]) : 0.f;
                v[i] = e; s += e;
            }
        } else {
            #pragma unroll
            for (int i = 0; i < 16; i++) v[i] = 0.f;
        }
        #pragma unroll
        for (int o = 16; o > 0; o >>= 1) s += __shfl_xor_sync(0xffffffffu, s, o);
        if (lane == 0) red[wid] = s;
        __syncthreads();
        if (t < 32) {
            float y = (lane < 16) ? red[lane] : 0.f;
            #pragma unroll
            for (int o = 8; o > 0; o >>= 1) y += __shfl_xor_sync(0xffffffffu, y, o);
            if (t == 0) { bcs = 1.0f / y; g_rsinv[row] = 1.0f / y; }
        }
        __syncthreads();
        float inv = bcs;
        #pragma unroll
        for (int i = 0; i < 16; i++) macc[i] += v[i] * inv;
    }
    float* orow = out + OFF_A + (size_t)bid*Mc;
    #pragma unroll
    for (int i = 0; i < 16; i++) {
        int o = j0 + i;
        if (!((mbits >> i) & 1)) orow[o] = 0.f;
    }
    #pragma unroll
    for (int i = 0; i < 16; i++) {
        int j = j0 + i;
        if (j < cnt) orow[g_midx[b][j]] = macc[i]*0.125f;
    }
}

// ---------- epilogue: 2 q per block, split-K reduce scaled by rsinv ----------
__global__ __launch_bounds__(256) void k_epilogue(const float* __restrict__ in_w,
        const float* __restrict__ in_b, const float* __restrict__ out_w,
        const float* __restrict__ out_b, const float* __restrict__ ln_g,
        const float* __restrict__ ln_b, float* __restrict__ out) {
    int b = blockIdx.x, q0 = blockIdx.y*2, t = threadIdx.x;
    __shared__ __align__(16) float cm[2][Hc][Dc];   // 32 KB
    __shared__ __align__(16) float co[2][Dc];       // 4 KB
    __shared__ float rsum[2][8], rsq[2][8], bcs[2][2];
    #pragma unroll
    for (int j = 0; j < 32; j++) {
        int idx = t + j*256; int qq = idx >> 12; int h = (idx >> 9) & 7; int e = idx & 511;
        size_t row = (size_t)b*HQc + h*Qc + q0 + qq;
        float s = 0.f;
        #pragma unroll
        for (int sp = 0; sp < 4; sp++) s += g_ctxp[sp][row*Dc + e];
        cm[qq][h][e] = s * g_rsinv[row];
    }
    __syncthreads();
    for (int f = t; f < Dc; f += 256) {
        int h = f >> 6;
        const float4* w  = (const float4*)(in_w + (size_t)(2*Dc + f)*Dc);
        const float4* c0 = (const float4*)cm[0][h];
        const float4* c1 = (const float4*)cm[1][h];
        float bias = in_b[2*Dc + f];
        float a0 = bias, a1 = bias;
        #pragma unroll 8
        for (int e = 0; e < Dc/4; e++) {
            float4 wv = w[e];
            float4 v0 = c0[e], v1 = c1[e];
            a0 += wv.x*v0.x + wv.y*v0.y + wv.z*v0.z + wv.w*v0.w;
            a1 += wv.x*v1.x + wv.y*v1.y + wv.z*v1.z + wv.w*v1.w;
        }
        co[0][f] = a0; co[1][f] = a1;
    }
    __syncthreads();
    float g0 = out[OFF_G + b*Qc + q0];
    float g1 = out[OFF_G + b*Qc + q0 + 1];
    const float4* co0 = (const float4*)co[0];
    const float4* co1 = (const float4*)co[1];
    float r[2][2];
    #pragma unroll
    for (int half = 0; half < 2; half++) {
        int d = t + half*256;
        const float4* w = (const float4*)(out_w + (size_t)d*Dc);
        float bias = out_b[d];
        float a0 = bias, a1 = bias;
        #pragma unroll 8
        for (int e = 0; e < Dc/4; e++) {
            float4 wv = w[e];
            float4 v0 = co0[e], v1 = co1[e];
            a0 += wv.x*v0.x + wv.y*v0.y + wv.z*v0.z + wv.w*v0.w;
            a1 += wv.x*v1.x + wv.y*v1.y + wv.z*v1.z + wv.w*v1.w;
        }
        r[0][half] = a0 * g0;
        r[1][half] = a1 * g1;
    }
    float s0 = r[0][0] + r[0][1], sq0 = r[0][0]*r[0][0] + r[0][1]*r[0][1];
    float s1 = r[1][0] + r[1][1], sq1 = r[1][0]*r[1][0] + r[1][1]*r[1][1];
    #pragma unroll
    for (int o = 16; o > 0; o >>= 1) {
        s0  += __shfl_xor_sync(0xffffffffu, s0,  o);
        sq0 += __shfl_xor_sync(0xffffffffu, sq0, o);
        s1  += __shfl_xor_sync(0xffffffffu, s1,  o);
        sq1 += __shfl_xor_sync(0xffffffffu, sq1, o);
    }
    if ((t & 31) == 0) {
        rsum[0][t >> 5] = s0; rsq[0][t >> 5] = sq0;
        rsum[1][t >> 5] = s1; rsq[1][t >> 5] = sq1;
    }
    __syncthreads();
    if (t < 2) {
        float S = 0.f, SQ = 0.f;
        #pragma unroll
        for (int i = 0; i < 8; i++) { S += rsum[t][i]; SQ += rsq[t][i]; }
        float mu = S * (1.0f/Dc);
        float var = SQ * (1.0f/Dc) - mu*mu;
        bcs[t][0] = mu; bcs[t][1] = rsqrtf(var + 1e-5f);
    }
    __syncthreads();
    #pragma unroll
    for (int qq = 0; qq < 2; qq++) {
        float mu = bcs[qq][0], rs = bcs[qq][1];
        size_t obase = OFF_R + ((size_t)(b*Qc + q0 + qq))*Dc;
        #pragma unroll
        for (int half = 0; half < 2; half++) {
            int d = t + half*256;
            out[obase + d] = (r[qq][half] - mu)*rs*ln_g[d] + ln_b[d];
        }
    }
}

// ---------- launch: single-stream main chain + convT fork ----------
extern "C" void kernel_launch(void* const* d_in, const int* in_sizes, int n_in,
                              void* d_out, int out_size) {
    const float* memory  = (const float*)d_in[0];
    const float* context = (const float*)d_in[1];
    const int*   mask    = (const int*)d_in[2];
    const float* qp      = (const float*)d_in[3];
    const float* ctx_w   = (const float*)d_in[4];
    const float* ctx_b   = (const float*)d_in[5];
    const float* in_w    = (const float*)d_in[6];
    const float* in_b    = (const float*)d_in[7];
    const float* out_w   = (const float*)d_in[8];
    const float* out_b   = (const float*)d_in[9];
    const float* ln_g    = (const float*)d_in[10];
    const float* ln_b    = (const float*)d_in[11];
    const float* gate_w  = (const float*)d_in[12];
    const float* gate_b  = (const float*)d_in[13];
    float* out = (float*)d_out;

    static cudaStream_t s1 = nullptr;
    static cudaEvent_t evA, evC;
    if (!s1) {
        cudaStreamCreateWithFlags(&s1, cudaStreamNonBlocking);
        cudaEventCreateWithFlags(&evA, cudaEventDisableTiming);
        cudaEventCreateWithFlags(&evC, cudaEventDisableTiming);
        cudaFuncSetAttribute(k_gemm<0>, cudaFuncAttributeMaxDynamicSharedMemorySize, GSM);
        cudaFuncSetAttribute(k_gemm<1>, cudaFuncAttributeMaxDynamicSharedMemorySize, GSM);
    }

    // fork: mask scan + gathered conversion concurrent with q-chain
    cudaEventRecord(evA, 0);
    cudaStreamWaitEvent(s1, evA, 0);

    k_pool_cq     <<<Bc, 512>>>(context, ctx_w, ctx_b, gate_w, gate_b, out);
    k_queries_qs  <<<Bc*Qc, 256>>>(qp, in_w, in_b, out);
    k_qk          <<<dim3(Hc, 32, 2), 128>>>(in_w);

    k_mask_scan   <<<Bc, 1024, 0, s1>>>(mask);
    k_convT       <<<dim3(128, 4, Bc), 256, 0, s1>>>(memory);
    cudaEventRecord(evC, s1);
    cudaStreamWaitEvent(0, evC, 0);

    k_gemm<0>     <<<dim3(64, 2, Bc), 256, GSM>>>();
    k_softmax_mean<<<Bc*Qc, 512>>>(mask, out);
    k_gemm<1>     <<<dim3(4, 2, Bc*4), 256, GSM>>>();
    k_epilogue    <<<dim3(Bc, 16), 256>>>(in_w, in_b, out_w, out_b, ln_g, ln_b, out);
}